// round 1
// baseline (speedup 1.0000x reference)
#include <cuda_runtime.h>
#include <cuda_bf16.h>
#include <math.h>

// ---------------------------------------------------------------------------
// Problem constants (fixed by the reference setup)
// ---------------------------------------------------------------------------
#define BS      2
#define QLEN    21760            // = 128*128 + 64*64 + 32*32 + 16*16
#define MROWS   (BS * QLEN)      // 43520
#define CDIM    256
#define HEADS   8
#define DHEAD   32
#define LEVELS  4
#define POINTS  4

// Level spatial sizes (square) and flattened start offsets
__device__ __constant__ int LVL_START[LEVELS] = {0, 16384, 20480, 21504};

// ---------------------------------------------------------------------------
// Scratch (static device globals; no runtime allocation allowed)
// ---------------------------------------------------------------------------
__device__ float g_val [MROWS * CDIM];       // value @ W_v + b_v          [m][c]
__device__ float g_off [MROWS * CDIM];       // query @ W_off + b_off      [m][256]
__device__ float g_attn[MROWS * (HEADS*16)]; // softmax(query@W_attn+b)    [m][128]
__device__ float g_samp[MROWS * CDIM];       // sampled output             [m][h*32+d]

// ---------------------------------------------------------------------------
// SGEMM: C[M,N] = A[M,K] @ B[K,N] + bias[N]
// A row-major [M,K], B row-major [K,N]. Requires M%128==0, N%128==0, K%8==0.
// 128x128 block tile, BK=8, 8x8 per thread, 256 threads.
// ---------------------------------------------------------------------------
#define GBM 128
#define GBN 128
#define GBK 8
#define GTM 8
#define GTN 8

__global__ __launch_bounds__(256, 2)
void sgemm_bias(const float* __restrict__ A, const float* __restrict__ B,
                const float* __restrict__ bias, float* __restrict__ C,
                int M, int N, int K)
{
    __shared__ float As[GBK][GBM + 4];
    __shared__ float Bs[GBK][GBN];

    const int tid = threadIdx.x;
    const int tx  = tid & 15;          // 0..15 -> N direction
    const int ty  = tid >> 4;          // 0..15 -> M direction
    const int rowBase = blockIdx.x * GBM;
    const int colBase = blockIdx.y * GBN;

    // A tile load mapping: 128x8 floats = 1024, 4 per thread (float4)
    const int aRow  = tid >> 1;        // 0..127
    const int aCol4 = (tid & 1) * 4;   // 0 or 4
    // B tile load mapping: 8x128 floats, 4 per thread (float4)
    const int bRow  = tid >> 5;        // 0..7
    const int bCol4 = (tid & 31) * 4;  // 0..124

    float acc[GTM][GTN];
#pragma unroll
    for (int i = 0; i < GTM; i++)
#pragma unroll
        for (int j = 0; j < GTN; j++) acc[i][j] = 0.f;

    for (int k0 = 0; k0 < K; k0 += GBK) {
        float4 a4 = *(const float4*)&A[(size_t)(rowBase + aRow) * K + k0 + aCol4];
        As[aCol4 + 0][aRow] = a4.x;
        As[aCol4 + 1][aRow] = a4.y;
        As[aCol4 + 2][aRow] = a4.z;
        As[aCol4 + 3][aRow] = a4.w;
        *(float4*)&Bs[bRow][bCol4] =
            *(const float4*)&B[(size_t)(k0 + bRow) * N + colBase + bCol4];
        __syncthreads();

#pragma unroll
        for (int k = 0; k < GBK; k++) {
            float4 a0 = *(const float4*)&As[k][ty * GTM];
            float4 a1 = *(const float4*)&As[k][ty * GTM + 4];
            float4 b0 = *(const float4*)&Bs[k][tx * GTN];
            float4 b1 = *(const float4*)&Bs[k][tx * GTN + 4];
            float ar[GTM] = {a0.x, a0.y, a0.z, a0.w, a1.x, a1.y, a1.z, a1.w};
            float br[GTN] = {b0.x, b0.y, b0.z, b0.w, b1.x, b1.y, b1.z, b1.w};
#pragma unroll
            for (int i = 0; i < GTM; i++)
#pragma unroll
                for (int j = 0; j < GTN; j++)
                    acc[i][j] = fmaf(ar[i], br[j], acc[i][j]);
        }
        __syncthreads();
    }

#pragma unroll
    for (int i = 0; i < GTM; i++) {
        const int r = rowBase + ty * GTM + i;
#pragma unroll
        for (int j4 = 0; j4 < GTN; j4 += 4) {
            const int c = colBase + tx * GTN + j4;
            float4 o;
            o.x = acc[i][j4 + 0] + bias[c + 0];
            o.y = acc[i][j4 + 1] + bias[c + 1];
            o.z = acc[i][j4 + 2] + bias[c + 2];
            o.w = acc[i][j4 + 3] + bias[c + 3];
            *(float4*)&C[(size_t)r * N + c] = o;
        }
    }
}

// ---------------------------------------------------------------------------
// Softmax over groups of 16 (L*P) per (m, head). rows = MROWS*HEADS.
// ---------------------------------------------------------------------------
__global__ void softmax16_kernel(float* __restrict__ attn, int rows)
{
    int r = blockIdx.x * blockDim.x + threadIdx.x;
    if (r >= rows) return;
    float* p = attn + (size_t)r * 16;
    float4 v[4];
#pragma unroll
    for (int i = 0; i < 4; i++) v[i] = *(float4*)&p[i * 4];

    float mx = -1e30f;
#pragma unroll
    for (int i = 0; i < 4; i++) {
        mx = fmaxf(mx, fmaxf(fmaxf(v[i].x, v[i].y), fmaxf(v[i].z, v[i].w)));
    }
    float s = 0.f;
#pragma unroll
    for (int i = 0; i < 4; i++) {
        v[i].x = expf(v[i].x - mx); s += v[i].x;
        v[i].y = expf(v[i].y - mx); s += v[i].y;
        v[i].z = expf(v[i].z - mx); s += v[i].z;
        v[i].w = expf(v[i].w - mx); s += v[i].w;
    }
    float inv = 1.f / s;
#pragma unroll
    for (int i = 0; i < 4; i++) {
        v[i].x *= inv; v[i].y *= inv; v[i].z *= inv; v[i].w *= inv;
        *(float4*)&p[i * 4] = v[i];
    }
}

// ---------------------------------------------------------------------------
// Deformable sampling. One block per m = b*QLEN+q, one warp per head,
// lane = channel within head. Output layout [m][h*32+d] (== [b,q,C]).
// ---------------------------------------------------------------------------
__global__ __launch_bounds__(HEADS * 32)
void sample_kernel(const float* __restrict__ val,
                   const float* __restrict__ off,
                   const float* __restrict__ attn,
                   const float* __restrict__ ref,
                   float* __restrict__ out)
{
    const int m    = blockIdx.x;
    const int b    = m / QLEN;
    const int head = threadIdx.x >> 5;
    const int lane = threadIdx.x & 31;

    const float* offq  = off  + (size_t)m * CDIM + head * (LEVELS * POINTS * 2);
    const float* attnq = attn + (size_t)m * (HEADS * 16) + head * 16;
    const float* refq  = ref  + (size_t)m * (LEVELS * 2);
    const float* valb  = val  + (size_t)b * QLEN * CDIM + head * DHEAD + lane;

    float acc = 0.f;

#pragma unroll
    for (int l = 0; l < LEVELS; l++) {
        const int   Wl = 128 >> l;       // square levels
        const float Wf = (float)Wl;
        const int   start = LVL_START[l];
        const float rx = __ldg(&refq[l * 2 + 0]);
        const float ry = __ldg(&refq[l * 2 + 1]);

#pragma unroll
        for (int p = 0; p < POINTS; p++) {
            const float ox = __ldg(&offq[(l * POINTS + p) * 2 + 0]);
            const float oy = __ldg(&offq[(l * POINTS + p) * 2 + 1]);
            const float a  = __ldg(&attnq[l * POINTS + p]);

            // loc = ref + off/[W,H];  x = loc.x*W - 0.5, y = loc.y*H - 0.5
            const float x = (rx + ox / Wf) * Wf - 0.5f;
            const float y = (ry + oy / Wf) * Wf - 0.5f;
            const float x0f = floorf(x), y0f = floorf(y);
            const int   x0 = (int)x0f,  y0 = (int)y0f;
            const float fx = x - x0f,   fy = y - y0f;

#pragma unroll
            for (int dy = 0; dy < 2; dy++) {
                const int yi = y0 + dy;
                if (yi < 0 || yi > Wl - 1) continue;
                const float wy = dy ? fy : (1.f - fy);
#pragma unroll
                for (int dx = 0; dx < 2; dx++) {
                    const int xi = x0 + dx;
                    if (xi < 0 || xi > Wl - 1) continue;
                    const float wx = dx ? fx : (1.f - fx);
                    const float w = wx * wy * a;
                    acc += w * __ldg(&valb[(size_t)(start + yi * Wl + xi) * CDIM]);
                }
            }
        }
    }
    out[(size_t)m * CDIM + head * DHEAD + lane] = acc;
}

// ---------------------------------------------------------------------------
// Launch
// ---------------------------------------------------------------------------
extern "C" void kernel_launch(void* const* d_in, const int* in_sizes, int n_in,
                              void* d_out, int out_size)
{
    const float* query  = (const float*)d_in[0];
    const float* value  = (const float*)d_in[1];
    const float* refpts = (const float*)d_in[2];
    // d_in[3] = spatial_shapes (int32) -- compile-time constants
    const float* W_off  = (const float*)d_in[4];
    const float* b_off  = (const float*)d_in[5];
    const float* W_attn = (const float*)d_in[6];
    const float* b_attn = (const float*)d_in[7];
    const float* W_v    = (const float*)d_in[8];
    const float* b_v    = (const float*)d_in[9];
    const float* W_out  = (const float*)d_in[10];
    const float* b_out  = (const float*)d_in[11];
    float* out = (float*)d_out;

    float* val  = nullptr; cudaGetSymbolAddress((void**)&val,  g_val);
    float* off  = nullptr; cudaGetSymbolAddress((void**)&off,  g_off);
    float* attn = nullptr; cudaGetSymbolAddress((void**)&attn, g_attn);
    float* samp = nullptr; cudaGetSymbolAddress((void**)&samp, g_samp);

    dim3 blk(256);
    dim3 grid2(MROWS / GBM, CDIM / GBN);   // N = 256
    dim3 grid1(MROWS / GBM, 128 / GBN);    // N = 128

    // 1) value projection
    sgemm_bias<<<grid2, blk>>>(value, W_v, b_v, val, MROWS, CDIM, CDIM);
    // 2) offsets
    sgemm_bias<<<grid2, blk>>>(query, W_off, b_off, off, MROWS, CDIM, CDIM);
    // 3) attention logits
    sgemm_bias<<<grid1, blk>>>(query, W_attn, b_attn, attn, MROWS, 128, CDIM);
    // 4) softmax over 16
    {
        int rows = MROWS * HEADS;
        int threads = 256;
        softmax16_kernel<<<(rows + threads - 1) / threads, threads>>>(attn, rows);
    }
    // 5) deformable bilinear sampling
    sample_kernel<<<MROWS, HEADS * 32>>>(val, off, attn, refpts, samp);
    // 6) output projection
    sgemm_bias<<<grid2, blk>>>(samp, W_out, b_out, out, MROWS, CDIM, CDIM);
}

// round 3
// speedup vs baseline: 1.4239x; 1.4239x over previous
#include <cuda_runtime.h>
#include <cuda_bf16.h>
#include <cstdint>
#include <math.h>

// ---------------------------------------------------------------------------
// Problem constants
// ---------------------------------------------------------------------------
#define BS      2
#define QLEN    21760            // 128^2 + 64^2 + 32^2 + 16^2
#define MROWS   (BS * QLEN)      // 43520
#define CDIM    256
#define HEADS   8
#define DHEAD   32
#define LEVELS  4
#define POINTS  4

__device__ __constant__ int LVL_START[LEVELS] = {0, 16384, 20480, 21504};

// ---------------------------------------------------------------------------
// Scratch (static device globals)
// ---------------------------------------------------------------------------
__device__ float g_val [MROWS * CDIM];        // value @ W_v + b_v (fp32)
__device__ float g_off [MROWS * CDIM];        // offsets (fp32)
__device__ float g_attn[MROWS * (HEADS*16)];  // attn logits -> softmax (fp32)

__device__ __nv_bfloat16 g_val_hi[MROWS * CDIM], g_val_lo[MROWS * CDIM];
__device__ __nv_bfloat16 g_q_hi  [MROWS * CDIM], g_q_lo  [MROWS * CDIM];
__device__ __nv_bfloat16 g_s_hi  [MROWS * CDIM], g_s_lo  [MROWS * CDIM];

// Transposed weights [N, K=256] bf16 hi/lo
__device__ __nv_bfloat16 g_wv_hi  [CDIM * CDIM], g_wv_lo  [CDIM * CDIM];
__device__ __nv_bfloat16 g_woff_hi[CDIM * CDIM], g_woff_lo[CDIM * CDIM];
__device__ __nv_bfloat16 g_wat_hi [128  * CDIM], g_wat_lo [128  * CDIM];
__device__ __nv_bfloat16 g_wout_hi[CDIM * CDIM], g_wout_lo[CDIM * CDIM];

// ---------------------------------------------------------------------------
// Helpers
// ---------------------------------------------------------------------------
__device__ __forceinline__ uint32_t smem_u32(const void* p) {
    uint32_t a;
    asm("{ .reg .u64 t; cvta.to.shared.u64 t, %1; cvt.u32.u64 %0, t; }" : "=r"(a) : "l"(p));
    return a;
}
#define SMEM_SWZ128(off) ((off) ^ (((off) >> 3) & 0x70))

__device__ __forceinline__ void ldsm4(uint32_t& r0, uint32_t& r1, uint32_t& r2, uint32_t& r3,
                                      uint32_t addr) {
    asm volatile("ldmatrix.sync.aligned.m8n8.x4.shared.b16 {%0,%1,%2,%3}, [%4];"
                 : "=r"(r0), "=r"(r1), "=r"(r2), "=r"(r3) : "r"(addr));
}
__device__ __forceinline__ void mma_bf16(float* d, const uint32_t* a, const uint32_t* b) {
    asm volatile(
        "mma.sync.aligned.m16n8k16.row.col.f32.bf16.bf16.f32 "
        "{%0,%1,%2,%3}, {%4,%5,%6,%7}, {%8,%9}, {%0,%1,%2,%3};"
        : "+f"(d[0]), "+f"(d[1]), "+f"(d[2]), "+f"(d[3])
        : "r"(a[0]), "r"(a[1]), "r"(a[2]), "r"(a[3]), "r"(b[0]), "r"(b[1]));
}

// ---------------------------------------------------------------------------
// Prep: fp32 -> (hi, lo) bf16 split
// ---------------------------------------------------------------------------
__global__ void split_bf16_kernel(const float* __restrict__ x,
                                  __nv_bfloat16* __restrict__ hi,
                                  __nv_bfloat16* __restrict__ lo, int n4)
{
    int i = blockIdx.x * blockDim.x + threadIdx.x;
    if (i >= n4) return;
    float4 v = ((const float4*)x)[i];
    __nv_bfloat16 h0 = __float2bfloat16(v.x), h1 = __float2bfloat16(v.y);
    __nv_bfloat16 h2 = __float2bfloat16(v.z), h3 = __float2bfloat16(v.w);
    __nv_bfloat16 l0 = __float2bfloat16(v.x - __bfloat162float(h0));
    __nv_bfloat16 l1 = __float2bfloat16(v.y - __bfloat162float(h1));
    __nv_bfloat16 l2 = __float2bfloat16(v.z - __bfloat162float(h2));
    __nv_bfloat16 l3 = __float2bfloat16(v.w - __bfloat162float(h3));
    ((__nv_bfloat162*)hi)[i*2+0] = __nv_bfloat162(h0, h1);
    ((__nv_bfloat162*)hi)[i*2+1] = __nv_bfloat162(h2, h3);
    ((__nv_bfloat162*)lo)[i*2+0] = __nv_bfloat162(l0, l1);
    ((__nv_bfloat162*)lo)[i*2+1] = __nv_bfloat162(l2, l3);
}

// W [K=256, N] fp32 -> Wt [N, 256] bf16 hi/lo
__global__ void transpose_split_kernel(const float* __restrict__ W,
                                       __nv_bfloat16* __restrict__ th,
                                       __nv_bfloat16* __restrict__ tl, int N)
{
    int n = blockIdx.x, k = threadIdx.x;
    float v = W[k * N + n];
    __nv_bfloat16 h = __float2bfloat16(v);
    th[n * 256 + k] = h;
    tl[n * 256 + k] = __float2bfloat16(v - __bfloat162float(h));
}

// ---------------------------------------------------------------------------
// HMMA GEMM: C[M,N] = (Ah+Al)[M,256] @ (Bh+Bl)[N,256]^T + bias
// 3-pass: Ah·Bh + Ah·Bl + Al·Bh. CTA 128x128, 8 warps (4x2), warp 32x64.
// K chunks of 64 through SW128-swizzled smem (4 tiles x 16KB = 64KB dyn).
// ---------------------------------------------------------------------------
#define GEMM_SMEM_BYTES (4 * 16384)

__global__ __launch_bounds__(256, 1)
void mma_gemm(const __nv_bfloat16* __restrict__ Ah, const __nv_bfloat16* __restrict__ Al,
              const __nv_bfloat16* __restrict__ Bh, const __nv_bfloat16* __restrict__ Bl,
              const float* __restrict__ bias, float* __restrict__ C, int Ncols)
{
    extern __shared__ char smem[];
    const uint32_t sb = smem_u32(smem);
    const uint32_t sAh = sb, sAl = sb + 16384, sBh = sb + 32768, sBl = sb + 49152;

    const int tid  = threadIdx.x;
    const int lane = tid & 31;
    const int wid  = tid >> 5;
    const int wm   = wid & 3;         // 0..3 -> M
    const int wn   = wid >> 2;        // 0..1 -> N
    const int mtile = blockIdx.x * 128;
    const int ntile = blockIdx.y * 128;

    float acc[2][8][4];
#pragma unroll
    for (int i = 0; i < 2; i++)
#pragma unroll
        for (int j = 0; j < 8; j++)
#pragma unroll
            for (int k = 0; k < 4; k++) acc[i][j][k] = 0.f;

    // ldmatrix per-thread offsets (row, 16B segment), swizzled
    const int a_row = wm * 32 + (lane & 7) + ((lane >> 3) & 1) * 8;  // + mt*16
    const int a_seg = (lane >> 4);                                    // + ks*2
    const int b_row = wn * 64 + (lane & 7) + (lane >> 4) * 8;         // + nt2*16
    const int b_seg = ((lane >> 3) & 1);                              // + ks*2

#pragma unroll 1
    for (int c = 0; c < 4; c++) {
        const int kc = c * 64;
        // Load 4 tiles (128 rows x 64 bf16 each) with SW128 swizzle
#pragma unroll
        for (int it = 0; it < 4; it++) {
            int idx = it * 256 + tid;
            int row = idx >> 3, seg = idx & 7;
            uint32_t so = SMEM_SWZ128((uint32_t)(row * 128 + seg * 16));
            size_t ga = (size_t)(mtile + row) * 256 + kc + seg * 8;
            size_t gb = (size_t)(ntile + row) * 256 + kc + seg * 8;
            *(uint4*)(smem + so)          = *(const uint4*)(Ah + ga);
            *(uint4*)(smem + 16384 + so)  = *(const uint4*)(Al + ga);
            *(uint4*)(smem + 32768 + so)  = *(const uint4*)(Bh + gb);
            *(uint4*)(smem + 49152 + so)  = *(const uint4*)(Bl + gb);
        }
        __syncthreads();

#pragma unroll
        for (int ks = 0; ks < 4; ks++) {
            uint32_t ah[2][4], al[2][4], bh[4][4], bl[4][4];
#pragma unroll
            for (int mt = 0; mt < 2; mt++) {
                uint32_t off = SMEM_SWZ128((uint32_t)((a_row + mt * 16) * 128 +
                                                      (a_seg + ks * 2) * 16));
                ldsm4(ah[mt][0], ah[mt][1], ah[mt][2], ah[mt][3], sAh + off);
                ldsm4(al[mt][0], al[mt][1], al[mt][2], al[mt][3], sAl + off);
            }
#pragma unroll
            for (int nt2 = 0; nt2 < 4; nt2++) {
                uint32_t off = SMEM_SWZ128((uint32_t)((b_row + nt2 * 16) * 128 +
                                                      (b_seg + ks * 2) * 16));
                ldsm4(bh[nt2][0], bh[nt2][1], bh[nt2][2], bh[nt2][3], sBh + off);
                ldsm4(bl[nt2][0], bl[nt2][1], bl[nt2][2], bl[nt2][3], sBl + off);
            }
#pragma unroll
            for (int mt = 0; mt < 2; mt++)
#pragma unroll
                for (int nt = 0; nt < 8; nt++) {
                    const uint32_t* bph = &bh[nt >> 1][(nt & 1) * 2];
                    const uint32_t* bpl = &bl[nt >> 1][(nt & 1) * 2];
                    mma_bf16(acc[mt][nt], ah[mt], bph);
                    mma_bf16(acc[mt][nt], ah[mt], bpl);
                    mma_bf16(acc[mt][nt], al[mt], bph);
                }
        }
        __syncthreads();
    }

    // Epilogue: direct fp32 stores + bias
#pragma unroll
    for (int mt = 0; mt < 2; mt++) {
        const int r0 = mtile + wm * 32 + mt * 16 + (lane >> 2);
#pragma unroll
        for (int nt = 0; nt < 8; nt++) {
            const int cc = ntile + wn * 64 + nt * 8 + (lane & 3) * 2;
            const float bx = __ldg(bias + cc), by = __ldg(bias + cc + 1);
            float2 o0 = {acc[mt][nt][0] + bx, acc[mt][nt][1] + by};
            float2 o1 = {acc[mt][nt][2] + bx, acc[mt][nt][3] + by};
            *(float2*)&C[(size_t)r0       * Ncols + cc] = o0;
            *(float2*)&C[(size_t)(r0 + 8) * Ncols + cc] = o1;
        }
    }
}

// ---------------------------------------------------------------------------
// Softmax over groups of 16 per (m, head)
// ---------------------------------------------------------------------------
__global__ void softmax16_kernel(float* __restrict__ attn, int rows)
{
    int r = blockIdx.x * blockDim.x + threadIdx.x;
    if (r >= rows) return;
    float* p = attn + (size_t)r * 16;
    float4 v[4];
#pragma unroll
    for (int i = 0; i < 4; i++) v[i] = *(float4*)&p[i * 4];
    float mx = -1e30f;
#pragma unroll
    for (int i = 0; i < 4; i++)
        mx = fmaxf(mx, fmaxf(fmaxf(v[i].x, v[i].y), fmaxf(v[i].z, v[i].w)));
    float s = 0.f;
#pragma unroll
    for (int i = 0; i < 4; i++) {
        v[i].x = expf(v[i].x - mx); s += v[i].x;
        v[i].y = expf(v[i].y - mx); s += v[i].y;
        v[i].z = expf(v[i].z - mx); s += v[i].z;
        v[i].w = expf(v[i].w - mx); s += v[i].w;
    }
    float inv = 1.f / s;
#pragma unroll
    for (int i = 0; i < 4; i++) {
        v[i].x *= inv; v[i].y *= inv; v[i].z *= inv; v[i].w *= inv;
        *(float4*)&p[i * 4] = v[i];
    }
}

// ---------------------------------------------------------------------------
// Deformable sampling -> bf16 hi/lo of sampled features
// ---------------------------------------------------------------------------
__global__ __launch_bounds__(HEADS * 32)
void sample_kernel(const float* __restrict__ val,
                   const float* __restrict__ off,
                   const float* __restrict__ attn,
                   const float* __restrict__ ref,
                   __nv_bfloat16* __restrict__ shi,
                   __nv_bfloat16* __restrict__ slo)
{
    const int m    = blockIdx.x;
    const int b    = m / QLEN;
    const int head = threadIdx.x >> 5;
    const int lane = threadIdx.x & 31;

    const float* offq  = off  + (size_t)m * CDIM + head * (LEVELS * POINTS * 2);
    const float* attnq = attn + (size_t)m * (HEADS * 16) + head * 16;
    const float* refq  = ref  + (size_t)m * (LEVELS * 2);
    const float* valb  = val  + (size_t)b * QLEN * CDIM + head * DHEAD + lane;

    float acc = 0.f;

#pragma unroll
    for (int l = 0; l < LEVELS; l++) {
        const int   Wl = 128 >> l;
        const float Wf = (float)Wl;
        const int   start = LVL_START[l];
        const float rx = __ldg(&refq[l * 2 + 0]);
        const float ry = __ldg(&refq[l * 2 + 1]);

#pragma unroll
        for (int p = 0; p < POINTS; p++) {
            const float ox = __ldg(&offq[(l * POINTS + p) * 2 + 0]);
            const float oy = __ldg(&offq[(l * POINTS + p) * 2 + 1]);
            const float a  = __ldg(&attnq[l * POINTS + p]);

            const float x = (rx + ox / Wf) * Wf - 0.5f;
            const float y = (ry + oy / Wf) * Wf - 0.5f;
            const float x0f = floorf(x), y0f = floorf(y);
            const int   x0 = (int)x0f,  y0 = (int)y0f;
            const float fx = x - x0f,   fy = y - y0f;

#pragma unroll
            for (int dy = 0; dy < 2; dy++) {
                const int yi = y0 + dy;
                if (yi < 0 || yi > Wl - 1) continue;
                const float wy = dy ? fy : (1.f - fy);
#pragma unroll
                for (int dx = 0; dx < 2; dx++) {
                    const int xi = x0 + dx;
                    if (xi < 0 || xi > Wl - 1) continue;
                    const float wx = dx ? fx : (1.f - fx);
                    const float w = wx * wy * a;
                    acc += w * __ldg(&valb[(size_t)(start + yi * Wl + xi) * CDIM]);
                }
            }
        }
    }
    const size_t oidx = (size_t)m * CDIM + head * DHEAD + lane;
    __nv_bfloat16 h = __float2bfloat16(acc);
    shi[oidx] = h;
    slo[oidx] = __float2bfloat16(acc - __bfloat162float(h));
}

// ---------------------------------------------------------------------------
// Launch
// ---------------------------------------------------------------------------
extern "C" void kernel_launch(void* const* d_in, const int* in_sizes, int n_in,
                              void* d_out, int out_size)
{
    const float* query  = (const float*)d_in[0];
    const float* value  = (const float*)d_in[1];
    const float* refpts = (const float*)d_in[2];
    const float* W_off  = (const float*)d_in[4];
    const float* b_off  = (const float*)d_in[5];
    const float* W_attn = (const float*)d_in[6];
    const float* b_attn = (const float*)d_in[7];
    const float* W_v    = (const float*)d_in[8];
    const float* b_v    = (const float*)d_in[9];
    const float* W_out  = (const float*)d_in[10];
    const float* b_out  = (const float*)d_in[11];
    float* out = (float*)d_out;

    float *val, *off, *attn;
    cudaGetSymbolAddress((void**)&val,  g_val);
    cudaGetSymbolAddress((void**)&off,  g_off);
    cudaGetSymbolAddress((void**)&attn, g_attn);
    __nv_bfloat16 *vhi, *vlo, *qhi, *qlo, *shi, *slo;
    cudaGetSymbolAddress((void**)&vhi, g_val_hi); cudaGetSymbolAddress((void**)&vlo, g_val_lo);
    cudaGetSymbolAddress((void**)&qhi, g_q_hi);   cudaGetSymbolAddress((void**)&qlo, g_q_lo);
    cudaGetSymbolAddress((void**)&shi, g_s_hi);   cudaGetSymbolAddress((void**)&slo, g_s_lo);
    __nv_bfloat16 *wvh, *wvl, *woh, *wol, *wah, *wal, *wuh, *wul;
    cudaGetSymbolAddress((void**)&wvh, g_wv_hi);   cudaGetSymbolAddress((void**)&wvl, g_wv_lo);
    cudaGetSymbolAddress((void**)&woh, g_woff_hi); cudaGetSymbolAddress((void**)&wol, g_woff_lo);
    cudaGetSymbolAddress((void**)&wah, g_wat_hi);  cudaGetSymbolAddress((void**)&wal, g_wat_lo);
    cudaGetSymbolAddress((void**)&wuh, g_wout_hi); cudaGetSymbolAddress((void**)&wul, g_wout_lo);

    cudaFuncSetAttribute(mma_gemm, cudaFuncAttributeMaxDynamicSharedMemorySize, GEMM_SMEM_BYTES);

    // 0) prep
    {
        int n4 = MROWS * CDIM / 4;
        int thr = 256, blks = (n4 + thr - 1) / thr;
        split_bf16_kernel<<<blks, thr>>>(value, vhi, vlo, n4);
        split_bf16_kernel<<<blks, thr>>>(query, qhi, qlo, n4);
        transpose_split_kernel<<<256, 256>>>(W_v,    wvh, wvl, 256);
        transpose_split_kernel<<<256, 256>>>(W_off,  woh, wol, 256);
        transpose_split_kernel<<<128, 256>>>(W_attn, wah, wal, 128);
        transpose_split_kernel<<<256, 256>>>(W_out,  wuh, wul, 256);
    }

    dim3 blk(256);
    dim3 gridN256(MROWS / 128, 2);
    dim3 gridN128(MROWS / 128, 1);

    mma_gemm<<<gridN256, blk, GEMM_SMEM_BYTES>>>(vhi, vlo, wvh, wvl, b_v, val, 256);
    mma_gemm<<<gridN256, blk, GEMM_SMEM_BYTES>>>(qhi, qlo, woh, wol, b_off, off, 256);
    mma_gemm<<<gridN128, blk, GEMM_SMEM_BYTES>>>(qhi, qlo, wah, wal, b_attn, attn, 128);
    {
        int rows = MROWS * HEADS;
        softmax16_kernel<<<(rows + 255) / 256, 256>>>(attn, rows);
    }
    sample_kernel<<<MROWS, HEADS * 32>>>(val, off, attn, refpts, shi, slo);
    mma_gemm<<<gridN256, blk, GEMM_SMEM_BYTES>>>(shi, slo, wuh, wul, b_out, out, 256);
}

// round 4
// speedup vs baseline: 1.5939x; 1.1193x over previous
#include <cuda_runtime.h>
#include <cuda_bf16.h>
#include <cstdint>
#include <math.h>

// ---------------------------------------------------------------------------
// Problem constants
// ---------------------------------------------------------------------------
#define BS      2
#define QLEN    21760            // 128^2 + 64^2 + 32^2 + 16^2
#define MROWS   (BS * QLEN)      // 43520
#define CDIM    256
#define HEADS   8
#define DHEAD   32
#define LEVELS  4
#define POINTS  4

__device__ __constant__ int LVL_START[LEVELS] = {0, 16384, 20480, 21504};

// ---------------------------------------------------------------------------
// Scratch (static device globals)
// ---------------------------------------------------------------------------
__device__ float g_val [MROWS * CDIM];        // value @ W_v + b_v (fp32)
__device__ float g_off [MROWS * CDIM];        // offsets (fp32)
__device__ float g_attn[MROWS * (HEADS*16)];  // attn logits (softmax in sampler)

__device__ __nv_bfloat16 g_val_hi[MROWS * CDIM], g_val_lo[MROWS * CDIM];
__device__ __nv_bfloat16 g_q_hi  [MROWS * CDIM], g_q_lo  [MROWS * CDIM];
__device__ __nv_bfloat16 g_s_hi  [MROWS * CDIM], g_s_lo  [MROWS * CDIM];

// Transposed weights [N, K=256] bf16 hi/lo
__device__ __nv_bfloat16 g_wv_hi  [CDIM * CDIM], g_wv_lo  [CDIM * CDIM];
__device__ __nv_bfloat16 g_woff_hi[CDIM * CDIM], g_woff_lo[CDIM * CDIM];
__device__ __nv_bfloat16 g_wat_hi [128  * CDIM], g_wat_lo [128  * CDIM];
__device__ __nv_bfloat16 g_wout_hi[CDIM * CDIM], g_wout_lo[CDIM * CDIM];

// ---------------------------------------------------------------------------
// Helpers
// ---------------------------------------------------------------------------
__device__ __forceinline__ uint32_t smem_u32(const void* p) {
    uint32_t a;
    asm("{ .reg .u64 t; cvta.to.shared.u64 t, %1; cvt.u32.u64 %0, t; }" : "=r"(a) : "l"(p));
    return a;
}
#define SMEM_SWZ128(off) ((off) ^ (((off) >> 3) & 0x70))

__device__ __forceinline__ void ldsm4(uint32_t& r0, uint32_t& r1, uint32_t& r2, uint32_t& r3,
                                      uint32_t addr) {
    asm volatile("ldmatrix.sync.aligned.m8n8.x4.shared.b16 {%0,%1,%2,%3}, [%4];"
                 : "=r"(r0), "=r"(r1), "=r"(r2), "=r"(r3) : "r"(addr));
}
__device__ __forceinline__ void mma_bf16(float* d, const uint32_t* a, const uint32_t* b) {
    asm volatile(
        "mma.sync.aligned.m16n8k16.row.col.f32.bf16.bf16.f32 "
        "{%0,%1,%2,%3}, {%4,%5,%6,%7}, {%8,%9}, {%0,%1,%2,%3};"
        : "+f"(d[0]), "+f"(d[1]), "+f"(d[2]), "+f"(d[3])
        : "r"(a[0]), "r"(a[1]), "r"(a[2]), "r"(a[3]), "r"(b[0]), "r"(b[1]));
}
#define CP_ASYNC16(dst_u32, src_ptr) \
    asm volatile("cp.async.cg.shared.global [%0], [%1], 16;" :: "r"(dst_u32), "l"(src_ptr))
#define CP_COMMIT()  asm volatile("cp.async.commit_group;" ::: "memory")
#define CP_WAIT0()   asm volatile("cp.async.wait_group 0;" ::: "memory")

// ---------------------------------------------------------------------------
// Prep (fused): fp32 -> (hi, lo) bf16 split for value & query
// ---------------------------------------------------------------------------
__global__ void split_all_kernel(const float* __restrict__ value,
                                 const float* __restrict__ query,
                                 __nv_bfloat16* __restrict__ vhi, __nv_bfloat16* __restrict__ vlo,
                                 __nv_bfloat16* __restrict__ qhi, __nv_bfloat16* __restrict__ qlo,
                                 int n4)
{
    int i = blockIdx.x * blockDim.x + threadIdx.x;
    if (i >= n4) return;
    const float* x = blockIdx.y ? query : value;
    __nv_bfloat16* hi = blockIdx.y ? qhi : vhi;
    __nv_bfloat16* lo = blockIdx.y ? qlo : vlo;
    float4 v = ((const float4*)x)[i];
    __nv_bfloat16 h0 = __float2bfloat16(v.x), h1 = __float2bfloat16(v.y);
    __nv_bfloat16 h2 = __float2bfloat16(v.z), h3 = __float2bfloat16(v.w);
    ((__nv_bfloat162*)hi)[i*2+0] = __nv_bfloat162(h0, h1);
    ((__nv_bfloat162*)hi)[i*2+1] = __nv_bfloat162(h2, h3);
    ((__nv_bfloat162*)lo)[i*2+0] = __nv_bfloat162(__float2bfloat16(v.x - __bfloat162float(h0)),
                                                  __float2bfloat16(v.y - __bfloat162float(h1)));
    ((__nv_bfloat162*)lo)[i*2+1] = __nv_bfloat162(__float2bfloat16(v.z - __bfloat162float(h2)),
                                                  __float2bfloat16(v.w - __bfloat162float(h3)));
}

// Fused weight transpose+split: y selects which weight. W [K=256, N] -> Wt [N,256] hi/lo
__global__ void transpose_split_all(const float* __restrict__ Wv,
                                    const float* __restrict__ Woff,
                                    const float* __restrict__ Wattn,
                                    const float* __restrict__ Wout,
                                    __nv_bfloat16* __restrict__ vh, __nv_bfloat16* __restrict__ vl,
                                    __nv_bfloat16* __restrict__ oh, __nv_bfloat16* __restrict__ ol,
                                    __nv_bfloat16* __restrict__ ah, __nv_bfloat16* __restrict__ al,
                                    __nv_bfloat16* __restrict__ uh, __nv_bfloat16* __restrict__ ul)
{
    const int which = blockIdx.y;
    const int n = blockIdx.x;
    const int k = threadIdx.x;
    const float* W; __nv_bfloat16 *th, *tl; int N;
    switch (which) {
        case 0: W = Wv;   th = vh; tl = vl; N = 256; break;
        case 1: W = Woff; th = oh; tl = ol; N = 256; break;
        case 2: W = Wattn;th = ah; tl = al; N = 128; break;
        default:W = Wout; th = uh; tl = ul; N = 256; break;
    }
    if (n >= N) return;
    float v = W[k * N + n];
    __nv_bfloat16 h = __float2bfloat16(v);
    th[n * 256 + k] = h;
    tl[n * 256 + k] = __float2bfloat16(v - __bfloat162float(h));
}

// ---------------------------------------------------------------------------
// HMMA GEMM: C[M,N] = (Ah+Al)[M,256] @ (Bh+Bl)[N,256]^T + bias  (3-pass hi/lo)
// CTA 128x128, 8 warps (4x2), warp 32x64. K chunks of 64, SW128 smem, cp.async.
// ---------------------------------------------------------------------------
#define GEMM_SMEM_BYTES (4 * 16384)

__global__ __launch_bounds__(256, 2)
void mma_gemm(const __nv_bfloat16* __restrict__ Ah, const __nv_bfloat16* __restrict__ Al,
              const __nv_bfloat16* __restrict__ Bh, const __nv_bfloat16* __restrict__ Bl,
              const float* __restrict__ bias, float* __restrict__ C, int Ncols)
{
    extern __shared__ char smem[];
    const uint32_t sb = smem_u32(smem);
    const uint32_t sAh = sb, sAl = sb + 16384, sBh = sb + 32768, sBl = sb + 49152;

    const int tid  = threadIdx.x;
    const int lane = tid & 31;
    const int wid  = tid >> 5;
    const int wm   = wid & 3;         // 0..3 -> M
    const int wn   = wid >> 2;        // 0..1 -> N
    const int mtile = blockIdx.x * 128;
    const int ntile = blockIdx.y * 128;

    float acc[2][8][4];
#pragma unroll
    for (int i = 0; i < 2; i++)
#pragma unroll
        for (int j = 0; j < 8; j++)
#pragma unroll
            for (int k = 0; k < 4; k++) acc[i][j][k] = 0.f;

    const int a_row = wm * 32 + (lane & 7) + ((lane >> 3) & 1) * 8;
    const int a_seg = (lane >> 4);
    const int b_row = wn * 64 + (lane & 7) + (lane >> 4) * 8;
    const int b_seg = ((lane >> 3) & 1);

    // cp.async source/dst mapping (per thread: 4 iters x 4 arrays)
    const int c_row = tid >> 1;               // 0..127 (x4 via iter)
    const int c_seg = (tid & 1) * 4;          // 0 or 4 (two segs per iter? no: seg pairs)

#pragma unroll 1
    for (int c = 0; c < 4; c++) {
        const int kc = c * 64;
#pragma unroll
        for (int it = 0; it < 4; it++) {
            int idx = it * 256 + tid;
            int row = idx >> 3, seg = idx & 7;
            uint32_t so = SMEM_SWZ128((uint32_t)(row * 128 + seg * 16));
            size_t ga = (size_t)(mtile + row) * 256 + kc + seg * 8;
            size_t gb = (size_t)(ntile + row) * 256 + kc + seg * 8;
            CP_ASYNC16(sAh + so, Ah + ga);
            CP_ASYNC16(sAl + so, Al + ga);
            CP_ASYNC16(sBh + so, Bh + gb);
            CP_ASYNC16(sBl + so, Bl + gb);
        }
        CP_COMMIT();
        CP_WAIT0();
        __syncthreads();

#pragma unroll
        for (int ks = 0; ks < 4; ks++) {
            uint32_t ah[2][4], al[2][4];
#pragma unroll
            for (int mt = 0; mt < 2; mt++) {
                uint32_t off = SMEM_SWZ128((uint32_t)((a_row + mt * 16) * 128 +
                                                      (a_seg + ks * 2) * 16));
                ldsm4(ah[mt][0], ah[mt][1], ah[mt][2], ah[mt][3], sAh + off);
                ldsm4(al[mt][0], al[mt][1], al[mt][2], al[mt][3], sAl + off);
            }
#pragma unroll
            for (int nt2 = 0; nt2 < 4; nt2++) {
                uint32_t off = SMEM_SWZ128((uint32_t)((b_row + nt2 * 16) * 128 +
                                                      (b_seg + ks * 2) * 16));
                uint32_t bh[4], bl[4];
                ldsm4(bh[0], bh[1], bh[2], bh[3], sBh + off);
                ldsm4(bl[0], bl[1], bl[2], bl[3], sBl + off);
#pragma unroll
                for (int mt = 0; mt < 2; mt++)
#pragma unroll
                    for (int half = 0; half < 2; half++) {
                        float* a4 = acc[mt][nt2 * 2 + half];
                        mma_bf16(a4, ah[mt], &bh[half * 2]);
                        mma_bf16(a4, ah[mt], &bl[half * 2]);
                        mma_bf16(a4, al[mt], &bh[half * 2]);
                    }
            }
        }
        __syncthreads();
    }
    (void)c_row; (void)c_seg;

#pragma unroll
    for (int mt = 0; mt < 2; mt++) {
        const int r0 = mtile + wm * 32 + mt * 16 + (lane >> 2);
#pragma unroll
        for (int nt = 0; nt < 8; nt++) {
            const int cc = ntile + wn * 64 + nt * 8 + (lane & 3) * 2;
            const float bx = __ldg(bias + cc), by = __ldg(bias + cc + 1);
            float2 o0 = {acc[mt][nt][0] + bx, acc[mt][nt][1] + by};
            float2 o1 = {acc[mt][nt][2] + bx, acc[mt][nt][3] + by};
            *(float2*)&C[(size_t)r0       * Ncols + cc] = o0;
            *(float2*)&C[(size_t)(r0 + 8) * Ncols + cc] = o1;
        }
    }
}

// ---------------------------------------------------------------------------
// Deformable sampling with inline softmax -> bf16 hi/lo outputs
// One block per m, one warp per head, lane = channel.
// ---------------------------------------------------------------------------
__global__ __launch_bounds__(HEADS * 32)
void sample_kernel(const float* __restrict__ val,
                   const float* __restrict__ off,
                   const float* __restrict__ logits,
                   const float* __restrict__ ref,
                   __nv_bfloat16* __restrict__ shi,
                   __nv_bfloat16* __restrict__ slo)
{
    const int m    = blockIdx.x;
    const int b    = m / QLEN;
    const int head = threadIdx.x >> 5;
    const int lane = threadIdx.x & 31;

    // --- inline softmax over this head's 16 logits (register-resident) ---
    const float* logq = logits + (size_t)m * (HEADS * 16) + head * 16;
    float lg = __ldg(&logq[lane & 15]);
    float mx = lg;
#pragma unroll
    for (int d = 1; d < 16; d <<= 1) mx = fmaxf(mx, __shfl_xor_sync(~0u, mx, d));
    float e = expf(lg - mx);
    float s = e;
#pragma unroll
    for (int d = 1; d < 16; d <<= 1) s += __shfl_xor_sync(~0u, s, d);
    const float a_reg = e / s;          // lane i (mod 16) holds attn weight i

    // --- offsets register-resident: lane holds off[lane] (32 floats) ---
    const float* offq = off + (size_t)m * CDIM + head * (LEVELS * POINTS * 2);
    const float ov = __ldg(&offq[lane]);

    const float* refq = ref + (size_t)m * (LEVELS * 2);
    const float rv = __ldg(&refq[lane & 7]);

    const float* valb = val + (size_t)b * QLEN * CDIM + head * DHEAD + lane;

    float acc0 = 0.f, acc1 = 0.f;

#pragma unroll
    for (int l = 0; l < LEVELS; l++) {
        const int   Wl = 128 >> l;
        const float Wf = (float)Wl;
        const int   start = LVL_START[l];
        const float rx = __shfl_sync(~0u, rv, 2 * l);
        const float ry = __shfl_sync(~0u, rv, 2 * l + 1);

#pragma unroll
        for (int p = 0; p < POINTS; p++) {
            const int lp = l * POINTS + p;
            const float ox = __shfl_sync(~0u, ov, 2 * lp);
            const float oy = __shfl_sync(~0u, ov, 2 * lp + 1);
            const float a  = __shfl_sync(~0u, a_reg, lp);

            const float x = (rx + ox / Wf) * Wf - 0.5f;
            const float y = (ry + oy / Wf) * Wf - 0.5f;
            const float x0f = floorf(x), y0f = floorf(y);
            const int   x0 = (int)x0f,  y0 = (int)y0f;
            const float fx = x - x0f,   fy = y - y0f;

#pragma unroll
            for (int dy = 0; dy < 2; dy++) {
                const int yi = y0 + dy;
                if (yi < 0 || yi > Wl - 1) continue;
                const float wy = dy ? fy : (1.f - fy);
#pragma unroll
                for (int dx = 0; dx < 2; dx++) {
                    const int xi = x0 + dx;
                    if (xi < 0 || xi > Wl - 1) continue;
                    const float wx = dx ? fx : (1.f - fx);
                    const float w = wx * wy * a;
                    const float v = __ldg(&valb[(size_t)(start + yi * Wl + xi) * CDIM]);
                    if (dx) acc1 += w * v; else acc0 += w * v;
                }
            }
        }
    }
    const float acc = acc0 + acc1;
    const size_t oidx = (size_t)m * CDIM + head * DHEAD + lane;
    __nv_bfloat16 h = __float2bfloat16(acc);
    shi[oidx] = h;
    slo[oidx] = __float2bfloat16(acc - __bfloat162float(h));
}

// ---------------------------------------------------------------------------
// Launch
// ---------------------------------------------------------------------------
extern "C" void kernel_launch(void* const* d_in, const int* in_sizes, int n_in,
                              void* d_out, int out_size)
{
    const float* query  = (const float*)d_in[0];
    const float* value  = (const float*)d_in[1];
    const float* refpts = (const float*)d_in[2];
    const float* W_off  = (const float*)d_in[4];
    const float* b_off  = (const float*)d_in[5];
    const float* W_attn = (const float*)d_in[6];
    const float* b_attn = (const float*)d_in[7];
    const float* W_v    = (const float*)d_in[8];
    const float* b_v    = (const float*)d_in[9];
    const float* W_out  = (const float*)d_in[10];
    const float* b_out  = (const float*)d_in[11];
    float* out = (float*)d_out;

    float *val, *off, *attn;
    cudaGetSymbolAddress((void**)&val,  g_val);
    cudaGetSymbolAddress((void**)&off,  g_off);
    cudaGetSymbolAddress((void**)&attn, g_attn);
    __nv_bfloat16 *vhi, *vlo, *qhi, *qlo, *shi, *slo;
    cudaGetSymbolAddress((void**)&vhi, g_val_hi); cudaGetSymbolAddress((void**)&vlo, g_val_lo);
    cudaGetSymbolAddress((void**)&qhi, g_q_hi);   cudaGetSymbolAddress((void**)&qlo, g_q_lo);
    cudaGetSymbolAddress((void**)&shi, g_s_hi);   cudaGetSymbolAddress((void**)&slo, g_s_lo);
    __nv_bfloat16 *wvh, *wvl, *woh, *wol, *wah, *wal, *wuh, *wul;
    cudaGetSymbolAddress((void**)&wvh, g_wv_hi);   cudaGetSymbolAddress((void**)&wvl, g_wv_lo);
    cudaGetSymbolAddress((void**)&woh, g_woff_hi); cudaGetSymbolAddress((void**)&wol, g_woff_lo);
    cudaGetSymbolAddress((void**)&wah, g_wat_hi);  cudaGetSymbolAddress((void**)&wal, g_wat_lo);
    cudaGetSymbolAddress((void**)&wuh, g_wout_hi); cudaGetSymbolAddress((void**)&wul, g_wout_lo);

    cudaFuncSetAttribute(mma_gemm, cudaFuncAttributeMaxDynamicSharedMemorySize, GEMM_SMEM_BYTES);

    // L0: fused weight transpose+split
    transpose_split_all<<<dim3(256, 4), 256>>>(W_v, W_off, W_attn, W_out,
                                               wvh, wvl, woh, wol, wah, wal, wuh, wul);
    // L1: fused value+query split
    {
        int n4 = MROWS * CDIM / 4;
        split_all_kernel<<<dim3((n4 + 255) / 256, 2), 256>>>(value, query,
                                                             vhi, vlo, qhi, qlo, n4);
    }

    dim3 blk(256);
    dim3 gridN256(MROWS / 128, 2);
    dim3 gridN128(MROWS / 128, 1);

    // L2-L4: GEMMs
    mma_gemm<<<gridN256, blk, GEMM_SMEM_BYTES>>>(vhi, vlo, wvh, wvl, b_v, val, 256);
    mma_gemm<<<gridN256, blk, GEMM_SMEM_BYTES>>>(qhi, qlo, woh, wol, b_off, off, 256);
    mma_gemm<<<gridN128, blk, GEMM_SMEM_BYTES>>>(qhi, qlo, wah, wal, b_attn, attn, 128);
    // L5: sampler (profiled by ncu -s 5 -c 1)
    sample_kernel<<<MROWS, HEADS * 32>>>(val, off, attn, refpts, shi, slo);
    // L6: output projection
    mma_gemm<<<gridN256, blk, GEMM_SMEM_BYTES>>>(shi, slo, wuh, wul, b_out, out, 256);
}

// round 5
// speedup vs baseline: 1.5942x; 1.0002x over previous
#include <cuda_runtime.h>
#include <cuda_bf16.h>
#include <cuda_fp16.h>
#include <cstdint>
#include <math.h>

// ---------------------------------------------------------------------------
// Problem constants
// ---------------------------------------------------------------------------
#define BS      2
#define QLEN    21760            // 128^2 + 64^2 + 32^2 + 16^2
#define MROWS   (BS * QLEN)      // 43520
#define CDIM    256
#define HEADS   8
#define DHEAD   32
#define LEVELS  4
#define POINTS  4

__device__ __constant__ int LVL_START[LEVELS] = {0, 16384, 20480, 21504};

// ---------------------------------------------------------------------------
// Scratch (static device globals)
// ---------------------------------------------------------------------------
__device__ __half g_val_h[MROWS * CDIM];      // value @ W_v + b_v (fp16, sampler-only)
__device__ float g_off [MROWS * CDIM];        // offsets (fp32)
__device__ float g_attn[MROWS * (HEADS*16)];  // attn logits (softmax in sampler)

__device__ __nv_bfloat16 g_val_hi[MROWS * CDIM], g_val_lo[MROWS * CDIM];
__device__ __nv_bfloat16 g_q_hi  [MROWS * CDIM], g_q_lo  [MROWS * CDIM];
__device__ __nv_bfloat16 g_s_hi  [MROWS * CDIM], g_s_lo  [MROWS * CDIM];

// Transposed weights [N, K=256] bf16 hi/lo
__device__ __nv_bfloat16 g_wv_hi  [CDIM * CDIM], g_wv_lo  [CDIM * CDIM];
__device__ __nv_bfloat16 g_woff_hi[CDIM * CDIM], g_woff_lo[CDIM * CDIM];
__device__ __nv_bfloat16 g_wat_hi [128  * CDIM], g_wat_lo [128  * CDIM];
__device__ __nv_bfloat16 g_wout_hi[CDIM * CDIM], g_wout_lo[CDIM * CDIM];

// ---------------------------------------------------------------------------
// Helpers
// ---------------------------------------------------------------------------
__device__ __forceinline__ uint32_t smem_u32(const void* p) {
    uint32_t a;
    asm("{ .reg .u64 t; cvta.to.shared.u64 t, %1; cvt.u32.u64 %0, t; }" : "=r"(a) : "l"(p));
    return a;
}
#define SMEM_SWZ64(off) ((off) ^ (((off) >> 3) & 0x30))

__device__ __forceinline__ void ldsm4(uint32_t& r0, uint32_t& r1, uint32_t& r2, uint32_t& r3,
                                      uint32_t addr) {
    asm volatile("ldmatrix.sync.aligned.m8n8.x4.shared.b16 {%0,%1,%2,%3}, [%4];"
                 : "=r"(r0), "=r"(r1), "=r"(r2), "=r"(r3) : "r"(addr));
}
__device__ __forceinline__ void mma_bf16(float* d, const uint32_t* a, const uint32_t* b) {
    asm volatile(
        "mma.sync.aligned.m16n8k16.row.col.f32.bf16.bf16.f32 "
        "{%0,%1,%2,%3}, {%4,%5,%6,%7}, {%8,%9}, {%0,%1,%2,%3};"
        : "+f"(d[0]), "+f"(d[1]), "+f"(d[2]), "+f"(d[3])
        : "r"(a[0]), "r"(a[1]), "r"(a[2]), "r"(a[3]), "r"(b[0]), "r"(b[1]));
}
#define CP_ASYNC16(dst_u32, src_ptr) \
    asm volatile("cp.async.cg.shared.global [%0], [%1], 16;" :: "r"(dst_u32), "l"(src_ptr))
#define CP_COMMIT()  asm volatile("cp.async.commit_group;" ::: "memory")
#define CP_WAIT1()   asm volatile("cp.async.wait_group 1;" ::: "memory")
#define CP_WAIT0()   asm volatile("cp.async.wait_group 0;" ::: "memory")

// ---------------------------------------------------------------------------
// Prep (fused): fp32 -> (hi, lo) bf16 split for value & query
// ---------------------------------------------------------------------------
__global__ void split_all_kernel(const float* __restrict__ value,
                                 const float* __restrict__ query,
                                 __nv_bfloat16* __restrict__ vhi, __nv_bfloat16* __restrict__ vlo,
                                 __nv_bfloat16* __restrict__ qhi, __nv_bfloat16* __restrict__ qlo,
                                 int n4)
{
    int i = blockIdx.x * blockDim.x + threadIdx.x;
    if (i >= n4) return;
    const float* x = blockIdx.y ? query : value;
    __nv_bfloat16* hi = blockIdx.y ? qhi : vhi;
    __nv_bfloat16* lo = blockIdx.y ? qlo : vlo;
    float4 v = ((const float4*)x)[i];
    __nv_bfloat16 h0 = __float2bfloat16(v.x), h1 = __float2bfloat16(v.y);
    __nv_bfloat16 h2 = __float2bfloat16(v.z), h3 = __float2bfloat16(v.w);
    ((__nv_bfloat162*)hi)[i*2+0] = __nv_bfloat162(h0, h1);
    ((__nv_bfloat162*)hi)[i*2+1] = __nv_bfloat162(h2, h3);
    ((__nv_bfloat162*)lo)[i*2+0] = __nv_bfloat162(__float2bfloat16(v.x - __bfloat162float(h0)),
                                                  __float2bfloat16(v.y - __bfloat162float(h1)));
    ((__nv_bfloat162*)lo)[i*2+1] = __nv_bfloat162(__float2bfloat16(v.z - __bfloat162float(h2)),
                                                  __float2bfloat16(v.w - __bfloat162float(h3)));
}

// Fused weight transpose+split: W [K=256, N] -> Wt [N,256] hi/lo
__global__ void transpose_split_all(const float* __restrict__ Wv,
                                    const float* __restrict__ Woff,
                                    const float* __restrict__ Wattn,
                                    const float* __restrict__ Wout,
                                    __nv_bfloat16* __restrict__ vh, __nv_bfloat16* __restrict__ vl,
                                    __nv_bfloat16* __restrict__ oh, __nv_bfloat16* __restrict__ ol,
                                    __nv_bfloat16* __restrict__ ah, __nv_bfloat16* __restrict__ al,
                                    __nv_bfloat16* __restrict__ uh, __nv_bfloat16* __restrict__ ul)
{
    const int which = blockIdx.y;
    const int n = blockIdx.x;
    const int k = threadIdx.x;
    const float* W; __nv_bfloat16 *th, *tl; int N;
    switch (which) {
        case 0: W = Wv;   th = vh; tl = vl; N = 256; break;
        case 1: W = Woff; th = oh; tl = ol; N = 256; break;
        case 2: W = Wattn;th = ah; tl = al; N = 128; break;
        default:W = Wout; th = uh; tl = ul; N = 256; break;
    }
    if (n >= N) return;
    float v = W[k * N + n];
    __nv_bfloat16 h = __float2bfloat16(v);
    th[n * 256 + k] = h;
    tl[n * 256 + k] = __float2bfloat16(v - __bfloat162float(h));
}

// ---------------------------------------------------------------------------
// HMMA GEMM: C = (Ah+Al)[M,256] @ (Bh+Bl)[N,256]^T + bias  (3-pass hi/lo)
// CTA 128x128, 8 warps (4x2). K chunks of 32, 2-stage cp.async double buffer,
// SW64-swizzled smem (64B rows). Optional fp16 output (Ch != nullptr).
// ---------------------------------------------------------------------------
#define STAGE_BYTES 32768                      // 4 tiles x 8KB
#define GEMM_SMEM_BYTES (2 * STAGE_BYTES)

__global__ __launch_bounds__(256, 2)
void mma_gemm(const __nv_bfloat16* __restrict__ Ah, const __nv_bfloat16* __restrict__ Al,
              const __nv_bfloat16* __restrict__ Bh, const __nv_bfloat16* __restrict__ Bl,
              const float* __restrict__ bias, float* __restrict__ C,
              __half* __restrict__ Ch, int Ncols)
{
    extern __shared__ char smem[];
    const uint32_t sb = smem_u32(smem);

    const int tid  = threadIdx.x;
    const int lane = tid & 31;
    const int wid  = tid >> 5;
    const int wm   = wid & 3;
    const int wn   = wid >> 2;
    const int mtile = blockIdx.x * 128;
    const int ntile = blockIdx.y * 128;

    float acc[2][8][4];
#pragma unroll
    for (int i = 0; i < 2; i++)
#pragma unroll
        for (int j = 0; j < 8; j++)
#pragma unroll
            for (int k = 0; k < 4; k++) acc[i][j][k] = 0.f;

    // cp.async mapping: per array, 2 iters; idx -> row=idx>>2, seg16=idx&3
    const int ld_row = tid >> 2;           // +64 per iter... (idx=it*256+tid)
    const int ld_seg = tid & 3;
    (void)ld_row; (void)ld_seg;

    // ldmatrix per-thread base offsets
    const int a_row = wm * 32 + (lane & 7) + ((lane >> 3) & 1) * 8;  // + mt*16
    const int a_sg  = (lane >> 4);                                    // + ks*2
    const int b_row = wn * 64 + (lane & 7) + (lane >> 4) * 8;         // + nt2*16
    const int b_sg  = ((lane >> 3) & 1);                              // + ks*2

#define LOAD_STAGE(cc, buf) do {                                                   \
    const uint32_t st = sb + (buf) * STAGE_BYTES;                                  \
    const int kc = (cc) * 32;                                                      \
    _Pragma("unroll")                                                              \
    for (int it = 0; it < 2; it++) {                                               \
        int idx = it * 256 + tid;                                                  \
        int row = idx >> 2, seg = idx & 3;                                         \
        uint32_t so = SMEM_SWZ64((uint32_t)(row * 64 + seg * 16));                 \
        size_t ga = (size_t)(mtile + row) * 256 + kc + seg * 8;                    \
        size_t gb = (size_t)(ntile + row) * 256 + kc + seg * 8;                    \
        CP_ASYNC16(st + so,         Ah + ga);                                      \
        CP_ASYNC16(st + 8192 + so,  Al + ga);                                      \
        CP_ASYNC16(st + 16384 + so, Bh + gb);                                      \
        CP_ASYNC16(st + 24576 + so, Bl + gb);                                      \
    }                                                                              \
} while (0)

    LOAD_STAGE(0, 0);
    CP_COMMIT();

#pragma unroll 1
    for (int c = 0; c < 8; c++) {
        if (c < 7) {
            LOAD_STAGE(c + 1, (c + 1) & 1);
            CP_COMMIT();
            CP_WAIT1();
        } else {
            CP_WAIT0();
        }
        __syncthreads();

        const uint32_t st  = sb + (c & 1) * STAGE_BYTES;
        const uint32_t sAh = st, sAl = st + 8192, sBh = st + 16384, sBl = st + 24576;

#pragma unroll
        for (int ks = 0; ks < 2; ks++) {
            uint32_t ah[2][4], al[2][4];
#pragma unroll
            for (int mt = 0; mt < 2; mt++) {
                uint32_t off = SMEM_SWZ64((uint32_t)((a_row + mt * 16) * 64 +
                                                     (a_sg + ks * 2) * 16));
                ldsm4(ah[mt][0], ah[mt][1], ah[mt][2], ah[mt][3], sAh + off);
                ldsm4(al[mt][0], al[mt][1], al[mt][2], al[mt][3], sAl + off);
            }
#pragma unroll
            for (int nt2 = 0; nt2 < 4; nt2++) {
                uint32_t off = SMEM_SWZ64((uint32_t)((b_row + nt2 * 16) * 64 +
                                                     (b_sg + ks * 2) * 16));
                uint32_t bh[4], bl[4];
                ldsm4(bh[0], bh[1], bh[2], bh[3], sBh + off);
                ldsm4(bl[0], bl[1], bl[2], bl[3], sBl + off);
#pragma unroll
                for (int mt = 0; mt < 2; mt++)
#pragma unroll
                    for (int half = 0; half < 2; half++) {
                        float* a4 = acc[mt][nt2 * 2 + half];
                        mma_bf16(a4, ah[mt], &bh[half * 2]);
                        mma_bf16(a4, ah[mt], &bl[half * 2]);
                        mma_bf16(a4, al[mt], &bh[half * 2]);
                    }
            }
        }
        __syncthreads();
    }
#undef LOAD_STAGE

    if (Ch) {
#pragma unroll
        for (int mt = 0; mt < 2; mt++) {
            const int r0 = mtile + wm * 32 + mt * 16 + (lane >> 2);
#pragma unroll
            for (int nt = 0; nt < 8; nt++) {
                const int cc = ntile + wn * 64 + nt * 8 + (lane & 3) * 2;
                const float bx = __ldg(bias + cc), by = __ldg(bias + cc + 1);
                __half2 h0 = __floats2half2_rn(acc[mt][nt][0] + bx, acc[mt][nt][1] + by);
                __half2 h1 = __floats2half2_rn(acc[mt][nt][2] + bx, acc[mt][nt][3] + by);
                *(__half2*)&Ch[(size_t)r0       * Ncols + cc] = h0;
                *(__half2*)&Ch[(size_t)(r0 + 8) * Ncols + cc] = h1;
            }
        }
    } else {
#pragma unroll
        for (int mt = 0; mt < 2; mt++) {
            const int r0 = mtile + wm * 32 + mt * 16 + (lane >> 2);
#pragma unroll
            for (int nt = 0; nt < 8; nt++) {
                const int cc = ntile + wn * 64 + nt * 8 + (lane & 3) * 2;
                const float bx = __ldg(bias + cc), by = __ldg(bias + cc + 1);
                float2 o0 = {acc[mt][nt][0] + bx, acc[mt][nt][1] + by};
                float2 o1 = {acc[mt][nt][2] + bx, acc[mt][nt][3] + by};
                *(float2*)&C[(size_t)r0       * Ncols + cc] = o0;
                *(float2*)&C[(size_t)(r0 + 8) * Ncols + cc] = o1;
            }
        }
    }
}

// ---------------------------------------------------------------------------
// Deformable sampling (fp16 value table) with inline softmax -> bf16 hi/lo
// ---------------------------------------------------------------------------
__global__ __launch_bounds__(HEADS * 32)
void sample_kernel(const __half* __restrict__ valh,
                   const float* __restrict__ off,
                   const float* __restrict__ logits,
                   const float* __restrict__ ref,
                   __nv_bfloat16* __restrict__ shi,
                   __nv_bfloat16* __restrict__ slo)
{
    const int m    = blockIdx.x;
    const int b    = m / QLEN;
    const int head = threadIdx.x >> 5;
    const int lane = threadIdx.x & 31;

    // inline softmax over this head's 16 logits
    const float* logq = logits + (size_t)m * (HEADS * 16) + head * 16;
    float lg = __ldg(&logq[lane & 15]);
    float mx = lg;
#pragma unroll
    for (int d = 1; d < 16; d <<= 1) mx = fmaxf(mx, __shfl_xor_sync(~0u, mx, d));
    float e = expf(lg - mx);
    float s = e;
#pragma unroll
    for (int d = 1; d < 16; d <<= 1) s += __shfl_xor_sync(~0u, s, d);
    const float a_reg = e / s;

    const float* offq = off + (size_t)m * CDIM + head * (LEVELS * POINTS * 2);
    const float ov = __ldg(&offq[lane]);
    const float* refq = ref + (size_t)m * (LEVELS * 2);
    const float rv = __ldg(&refq[lane & 7]);

    const __half* valb = valh + (size_t)b * QLEN * CDIM + head * DHEAD + lane;

    float acc0 = 0.f, acc1 = 0.f;

#pragma unroll
    for (int l = 0; l < LEVELS; l++) {
        const int   Wl = 128 >> l;
        const float Wf = (float)Wl;
        const int   start = LVL_START[l];
        const float rx = __shfl_sync(~0u, rv, 2 * l);
        const float ry = __shfl_sync(~0u, rv, 2 * l + 1);

#pragma unroll
        for (int p = 0; p < POINTS; p++) {
            const int lp = l * POINTS + p;
            const float ox = __shfl_sync(~0u, ov, 2 * lp);
            const float oy = __shfl_sync(~0u, ov, 2 * lp + 1);
            const float a  = __shfl_sync(~0u, a_reg, lp);

            const float x = (rx + ox / Wf) * Wf - 0.5f;
            const float y = (ry + oy / Wf) * Wf - 0.5f;
            const float x0f = floorf(x), y0f = floorf(y);
            const int   x0 = (int)x0f,  y0 = (int)y0f;
            const float fx = x - x0f,   fy = y - y0f;

#pragma unroll
            for (int dy = 0; dy < 2; dy++) {
                const int yi = y0 + dy;
                if (yi < 0 || yi > Wl - 1) continue;
                const float wy = dy ? fy : (1.f - fy);
#pragma unroll
                for (int dx = 0; dx < 2; dx++) {
                    const int xi = x0 + dx;
                    if (xi < 0 || xi > Wl - 1) continue;
                    const float wx = dx ? fx : (1.f - fx);
                    const float w = wx * wy * a;
                    const float v = __half2float(__ldg(&valb[(size_t)(start + yi * Wl + xi) * CDIM]));
                    if (dx) acc1 += w * v; else acc0 += w * v;
                }
            }
        }
    }
    const float acc = acc0 + acc1;
    const size_t oidx = (size_t)m * CDIM + head * DHEAD + lane;
    __nv_bfloat16 h = __float2bfloat16(acc);
    shi[oidx] = h;
    slo[oidx] = __float2bfloat16(acc - __bfloat162float(h));
}

// ---------------------------------------------------------------------------
// Launch
// ---------------------------------------------------------------------------
extern "C" void kernel_launch(void* const* d_in, const int* in_sizes, int n_in,
                              void* d_out, int out_size)
{
    const float* query  = (const float*)d_in[0];
    const float* value  = (const float*)d_in[1];
    const float* refpts = (const float*)d_in[2];
    const float* W_off  = (const float*)d_in[4];
    const float* b_off  = (const float*)d_in[5];
    const float* W_attn = (const float*)d_in[6];
    const float* b_attn = (const float*)d_in[7];
    const float* W_v    = (const float*)d_in[8];
    const float* b_v    = (const float*)d_in[9];
    const float* W_out  = (const float*)d_in[10];
    const float* b_out  = (const float*)d_in[11];
    float* out = (float*)d_out;

    float *off, *attn; __half* valh;
    cudaGetSymbolAddress((void**)&valh, g_val_h);
    cudaGetSymbolAddress((void**)&off,  g_off);
    cudaGetSymbolAddress((void**)&attn, g_attn);
    __nv_bfloat16 *vhi, *vlo, *qhi, *qlo, *shi, *slo;
    cudaGetSymbolAddress((void**)&vhi, g_val_hi); cudaGetSymbolAddress((void**)&vlo, g_val_lo);
    cudaGetSymbolAddress((void**)&qhi, g_q_hi);   cudaGetSymbolAddress((void**)&qlo, g_q_lo);
    cudaGetSymbolAddress((void**)&shi, g_s_hi);   cudaGetSymbolAddress((void**)&slo, g_s_lo);
    __nv_bfloat16 *wvh, *wvl, *woh, *wol, *wah, *wal, *wuh, *wul;
    cudaGetSymbolAddress((void**)&wvh, g_wv_hi);   cudaGetSymbolAddress((void**)&wvl, g_wv_lo);
    cudaGetSymbolAddress((void**)&woh, g_woff_hi); cudaGetSymbolAddress((void**)&wol, g_woff_lo);
    cudaGetSymbolAddress((void**)&wah, g_wat_hi);  cudaGetSymbolAddress((void**)&wal, g_wat_lo);
    cudaGetSymbolAddress((void**)&wuh, g_wout_hi); cudaGetSymbolAddress((void**)&wul, g_wout_lo);

    cudaFuncSetAttribute(mma_gemm, cudaFuncAttributeMaxDynamicSharedMemorySize, GEMM_SMEM_BYTES);

    // L0: fused weight transpose+split
    transpose_split_all<<<dim3(256, 4), 256>>>(W_v, W_off, W_attn, W_out,
                                               wvh, wvl, woh, wol, wah, wal, wuh, wul);
    // L1: fused value+query split
    {
        int n4 = MROWS * CDIM / 4;
        split_all_kernel<<<dim3((n4 + 255) / 256, 2), 256>>>(value, query,
                                                             vhi, vlo, qhi, qlo, n4);
    }

    dim3 blk(256);
    dim3 gridN256(MROWS / 128, 2);
    dim3 gridN128(MROWS / 128, 1);

    // L2: value projection -> fp16 table
    mma_gemm<<<gridN256, blk, GEMM_SMEM_BYTES>>>(vhi, vlo, wvh, wvl, b_v, nullptr, valh, 256);
    // L3: offsets
    mma_gemm<<<gridN256, blk, GEMM_SMEM_BYTES>>>(qhi, qlo, woh, wol, b_off, off, nullptr, 256);
    // L4: attn logits
    mma_gemm<<<gridN128, blk, GEMM_SMEM_BYTES>>>(qhi, qlo, wah, wal, b_attn, attn, nullptr, 128);
    // L5: sampler
    sample_kernel<<<MROWS, HEADS * 32>>>(valh, off, attn, refpts, shi, slo);
    // L6: output projection
    mma_gemm<<<gridN256, blk, GEMM_SMEM_BYTES>>>(shi, slo, wuh, wul, b_out, out, nullptr, 256);
}

// round 6
// speedup vs baseline: 2.2976x; 1.4412x over previous
#include <cuda_runtime.h>
#include <cuda_bf16.h>
#include <cuda_fp16.h>
#include <cstdint>
#include <math.h>

// ---------------------------------------------------------------------------
// Problem constants
// ---------------------------------------------------------------------------
#define BS      2
#define QLEN    21760            // 128^2 + 64^2 + 32^2 + 16^2
#define MROWS   (BS * QLEN)      // 43520
#define CDIM    256
#define HEADS   8
#define DHEAD   32
#define LEVELS  4
#define POINTS  4

// ---------------------------------------------------------------------------
// Scratch (static device globals)
// ---------------------------------------------------------------------------
__device__ __half g_val_h[MROWS * CDIM];      // value @ W_v + b_v (fp16, sampler-only)
__device__ float g_off [MROWS * CDIM];        // offsets (fp32)
__device__ float g_attn[MROWS * (HEADS*16)];  // attn logits (softmax in sampler)

__device__ __nv_bfloat16 g_val_hi[MROWS * CDIM], g_val_lo[MROWS * CDIM];
__device__ __nv_bfloat16 g_q_hi  [MROWS * CDIM], g_q_lo  [MROWS * CDIM];
__device__ __nv_bfloat16 g_s_hi  [MROWS * CDIM], g_s_lo  [MROWS * CDIM];

// Transposed weights [N, K=256] bf16 hi/lo
__device__ __nv_bfloat16 g_wv_hi  [CDIM * CDIM], g_wv_lo  [CDIM * CDIM];
__device__ __nv_bfloat16 g_woff_hi[CDIM * CDIM], g_woff_lo[CDIM * CDIM];
__device__ __nv_bfloat16 g_wat_hi [128  * CDIM], g_wat_lo [128  * CDIM];
__device__ __nv_bfloat16 g_wout_hi[CDIM * CDIM], g_wout_lo[CDIM * CDIM];

// ---------------------------------------------------------------------------
// Helpers
// ---------------------------------------------------------------------------
__device__ __forceinline__ uint32_t smem_u32(const void* p) {
    uint32_t a;
    asm("{ .reg .u64 t; cvta.to.shared.u64 t, %1; cvt.u32.u64 %0, t; }" : "=r"(a) : "l"(p));
    return a;
}
#define SMEM_SWZ64(off) ((off) ^ (((off) >> 3) & 0x30))

__device__ __forceinline__ void ldsm4(uint32_t& r0, uint32_t& r1, uint32_t& r2, uint32_t& r3,
                                      uint32_t addr) {
    asm volatile("ldmatrix.sync.aligned.m8n8.x4.shared.b16 {%0,%1,%2,%3}, [%4];"
                 : "=r"(r0), "=r"(r1), "=r"(r2), "=r"(r3) : "r"(addr));
}
__device__ __forceinline__ void mma_bf16(float* d, const uint32_t* a, const uint32_t* b) {
    asm volatile(
        "mma.sync.aligned.m16n8k16.row.col.f32.bf16.bf16.f32 "
        "{%0,%1,%2,%3}, {%4,%5,%6,%7}, {%8,%9}, {%0,%1,%2,%3};"
        : "+f"(d[0]), "+f"(d[1]), "+f"(d[2]), "+f"(d[3])
        : "r"(a[0]), "r"(a[1]), "r"(a[2]), "r"(a[3]), "r"(b[0]), "r"(b[1]));
}
#define CP_ASYNC16(dst_u32, src_ptr) \
    asm volatile("cp.async.cg.shared.global [%0], [%1], 16;" :: "r"(dst_u32), "l"(src_ptr))
#define CP_COMMIT()  asm volatile("cp.async.commit_group;" ::: "memory")
#define CP_WAIT1()   asm volatile("cp.async.wait_group 1;" ::: "memory")
#define CP_WAIT0()   asm volatile("cp.async.wait_group 0;" ::: "memory")

// ---------------------------------------------------------------------------
// Prep (fused): fp32 -> (hi, lo) bf16 split for value & query
// ---------------------------------------------------------------------------
__global__ void split_all_kernel(const float* __restrict__ value,
                                 const float* __restrict__ query,
                                 __nv_bfloat16* __restrict__ vhi, __nv_bfloat16* __restrict__ vlo,
                                 __nv_bfloat16* __restrict__ qhi, __nv_bfloat16* __restrict__ qlo,
                                 int n4)
{
    int i = blockIdx.x * blockDim.x + threadIdx.x;
    if (i >= n4) return;
    const float* x = blockIdx.y ? query : value;
    __nv_bfloat16* hi = blockIdx.y ? qhi : vhi;
    __nv_bfloat16* lo = blockIdx.y ? qlo : vlo;
    float4 v = ((const float4*)x)[i];
    __nv_bfloat16 h0 = __float2bfloat16(v.x), h1 = __float2bfloat16(v.y);
    __nv_bfloat16 h2 = __float2bfloat16(v.z), h3 = __float2bfloat16(v.w);
    ((__nv_bfloat162*)hi)[i*2+0] = __nv_bfloat162(h0, h1);
    ((__nv_bfloat162*)hi)[i*2+1] = __nv_bfloat162(h2, h3);
    ((__nv_bfloat162*)lo)[i*2+0] = __nv_bfloat162(__float2bfloat16(v.x - __bfloat162float(h0)),
                                                  __float2bfloat16(v.y - __bfloat162float(h1)));
    ((__nv_bfloat162*)lo)[i*2+1] = __nv_bfloat162(__float2bfloat16(v.z - __bfloat162float(h2)),
                                                  __float2bfloat16(v.w - __bfloat162float(h3)));
}

// Fused weight transpose+split: W [K=256, N] -> Wt [N,256] hi/lo
__global__ void transpose_split_all(const float* __restrict__ Wv,
                                    const float* __restrict__ Woff,
                                    const float* __restrict__ Wattn,
                                    const float* __restrict__ Wout,
                                    __nv_bfloat16* __restrict__ vh, __nv_bfloat16* __restrict__ vl,
                                    __nv_bfloat16* __restrict__ oh, __nv_bfloat16* __restrict__ ol,
                                    __nv_bfloat16* __restrict__ ah, __nv_bfloat16* __restrict__ al,
                                    __nv_bfloat16* __restrict__ uh, __nv_bfloat16* __restrict__ ul)
{
    const int which = blockIdx.y;
    const int n = blockIdx.x;
    const int k = threadIdx.x;
    const float* W; __nv_bfloat16 *th, *tl; int N;
    switch (which) {
        case 0: W = Wv;   th = vh; tl = vl; N = 256; break;
        case 1: W = Woff; th = oh; tl = ol; N = 256; break;
        case 2: W = Wattn;th = ah; tl = al; N = 128; break;
        default:W = Wout; th = uh; tl = ul; N = 256; break;
    }
    if (n >= N) return;
    float v = W[k * N + n];
    __nv_bfloat16 h = __float2bfloat16(v);
    th[n * 256 + k] = h;
    tl[n * 256 + k] = __float2bfloat16(v - __bfloat162float(h));
}

// ---------------------------------------------------------------------------
// HMMA GEMM (unchanged from R5): 3-pass hi/lo bf16, CTA 128x128, K=32 chunks,
// 2-stage cp.async, SW64 smem.
// ---------------------------------------------------------------------------
#define STAGE_BYTES 32768
#define GEMM_SMEM_BYTES (2 * STAGE_BYTES)

__global__ __launch_bounds__(256, 2)
void mma_gemm(const __nv_bfloat16* __restrict__ Ah, const __nv_bfloat16* __restrict__ Al,
              const __nv_bfloat16* __restrict__ Bh, const __nv_bfloat16* __restrict__ Bl,
              const float* __restrict__ bias, float* __restrict__ C,
              __half* __restrict__ Ch, int Ncols)
{
    extern __shared__ char smem[];
    const uint32_t sb = smem_u32(smem);

    const int tid  = threadIdx.x;
    const int lane = tid & 31;
    const int wid  = tid >> 5;
    const int wm   = wid & 3;
    const int wn   = wid >> 2;
    const int mtile = blockIdx.x * 128;
    const int ntile = blockIdx.y * 128;

    float acc[2][8][4];
#pragma unroll
    for (int i = 0; i < 2; i++)
#pragma unroll
        for (int j = 0; j < 8; j++)
#pragma unroll
            for (int k = 0; k < 4; k++) acc[i][j][k] = 0.f;

    const int a_row = wm * 32 + (lane & 7) + ((lane >> 3) & 1) * 8;
    const int a_sg  = (lane >> 4);
    const int b_row = wn * 64 + (lane & 7) + (lane >> 4) * 8;
    const int b_sg  = ((lane >> 3) & 1);

#define LOAD_STAGE(cc, buf) do {                                                   \
    const uint32_t st = sb + (buf) * STAGE_BYTES;                                  \
    const int kc = (cc) * 32;                                                      \
    _Pragma("unroll")                                                              \
    for (int it = 0; it < 2; it++) {                                               \
        int idx = it * 256 + tid;                                                  \
        int row = idx >> 2, seg = idx & 3;                                         \
        uint32_t so = SMEM_SWZ64((uint32_t)(row * 64 + seg * 16));                 \
        size_t ga = (size_t)(mtile + row) * 256 + kc + seg * 8;                    \
        size_t gb = (size_t)(ntile + row) * 256 + kc + seg * 8;                    \
        CP_ASYNC16(st + so,         Ah + ga);                                      \
        CP_ASYNC16(st + 8192 + so,  Al + ga);                                      \
        CP_ASYNC16(st + 16384 + so, Bh + gb);                                      \
        CP_ASYNC16(st + 24576 + so, Bl + gb);                                      \
    }                                                                              \
} while (0)

    LOAD_STAGE(0, 0);
    CP_COMMIT();

#pragma unroll 1
    for (int c = 0; c < 8; c++) {
        if (c < 7) {
            LOAD_STAGE(c + 1, (c + 1) & 1);
            CP_COMMIT();
            CP_WAIT1();
        } else {
            CP_WAIT0();
        }
        __syncthreads();

        const uint32_t st  = sb + (c & 1) * STAGE_BYTES;
        const uint32_t sAh = st, sAl = st + 8192, sBh = st + 16384, sBl = st + 24576;

#pragma unroll
        for (int ks = 0; ks < 2; ks++) {
            uint32_t ah[2][4], al[2][4];
#pragma unroll
            for (int mt = 0; mt < 2; mt++) {
                uint32_t off = SMEM_SWZ64((uint32_t)((a_row + mt * 16) * 64 +
                                                     (a_sg + ks * 2) * 16));
                ldsm4(ah[mt][0], ah[mt][1], ah[mt][2], ah[mt][3], sAh + off);
                ldsm4(al[mt][0], al[mt][1], al[mt][2], al[mt][3], sAl + off);
            }
#pragma unroll
            for (int nt2 = 0; nt2 < 4; nt2++) {
                uint32_t off = SMEM_SWZ64((uint32_t)((b_row + nt2 * 16) * 64 +
                                                     (b_sg + ks * 2) * 16));
                uint32_t bh[4], bl[4];
                ldsm4(bh[0], bh[1], bh[2], bh[3], sBh + off);
                ldsm4(bl[0], bl[1], bl[2], bl[3], sBl + off);
#pragma unroll
                for (int mt = 0; mt < 2; mt++)
#pragma unroll
                    for (int half = 0; half < 2; half++) {
                        float* a4 = acc[mt][nt2 * 2 + half];
                        mma_bf16(a4, ah[mt], &bh[half * 2]);
                        mma_bf16(a4, ah[mt], &bl[half * 2]);
                        mma_bf16(a4, al[mt], &bh[half * 2]);
                    }
            }
        }
        __syncthreads();
    }
#undef LOAD_STAGE

    if (Ch) {
#pragma unroll
        for (int mt = 0; mt < 2; mt++) {
            const int r0 = mtile + wm * 32 + mt * 16 + (lane >> 2);
#pragma unroll
            for (int nt = 0; nt < 8; nt++) {
                const int cc = ntile + wn * 64 + nt * 8 + (lane & 3) * 2;
                const float bx = __ldg(bias + cc), by = __ldg(bias + cc + 1);
                __half2 h0 = __floats2half2_rn(acc[mt][nt][0] + bx, acc[mt][nt][1] + by);
                __half2 h1 = __floats2half2_rn(acc[mt][nt][2] + bx, acc[mt][nt][3] + by);
                *(__half2*)&Ch[(size_t)r0       * Ncols + cc] = h0;
                *(__half2*)&Ch[(size_t)(r0 + 8) * Ncols + cc] = h1;
            }
        }
    } else {
#pragma unroll
        for (int mt = 0; mt < 2; mt++) {
            const int r0 = mtile + wm * 32 + mt * 16 + (lane >> 2);
#pragma unroll
            for (int nt = 0; nt < 8; nt++) {
                const int cc = ntile + wn * 64 + nt * 8 + (lane & 3) * 2;
                const float bx = __ldg(bias + cc), by = __ldg(bias + cc + 1);
                float2 o0 = {acc[mt][nt][0] + bx, acc[mt][nt][1] + by};
                float2 o1 = {acc[mt][nt][2] + bx, acc[mt][nt][3] + by};
                *(float2*)&C[(size_t)r0       * Ncols + cc] = o0;
                *(float2*)&C[(size_t)(r0 + 8) * Ncols + cc] = o1;
            }
        }
    }
}

// ---------------------------------------------------------------------------
// Deformable sampling, vectorized gathers.
// warp = head; lane -> (level g = lane>>3, channel-quad cp = lane&7).
// Each lane gathers 4 channels per LDG.64; 4 levels' points run concurrently.
// 16 gather LDGs per warp (was 64). Branch-free boundaries.
// ---------------------------------------------------------------------------
__global__ __launch_bounds__(HEADS * 32)
void sample_kernel(const __half* __restrict__ valh,
                   const float* __restrict__ off,
                   const float* __restrict__ logits,
                   const float* __restrict__ ref,
                   __nv_bfloat16* __restrict__ shi,
                   __nv_bfloat16* __restrict__ slo)
{
    const int m    = blockIdx.x;
    const int b    = m / QLEN;
    const int head = threadIdx.x >> 5;
    const int lane = threadIdx.x & 31;
    const int g    = lane >> 3;        // level handled by this lane's group
    const int cp   = lane & 7;         // channel quad: channels cp*4 .. cp*4+3

    // --- softmax over this head's 16 logits (register-resident) ---
    const float* logq = logits + (size_t)m * (HEADS * 16) + head * 16;
    float lg = __ldg(&logq[lane & 15]);
    float mx = lg;
#pragma unroll
    for (int d = 1; d < 16; d <<= 1) mx = fmaxf(mx, __shfl_xor_sync(~0u, mx, d));
    float e = expf(lg - mx);
    float s = e;
#pragma unroll
    for (int d = 1; d < 16; d <<= 1) s += __shfl_xor_sync(~0u, s, d);
    const float a_reg = e / s;          // lane i (mod 16) holds attn weight i

    // offsets (32 floats per head) and reference points (8 floats) in registers
    const float ov = __ldg(&off[(size_t)m * CDIM + head * 32 + lane]);
    const float rv = __ldg(&ref[(size_t)m * (LEVELS * 2) + (lane & 7)]);

    const int   Wl = 128 >> g;
    const float Wf = (float)Wl;
    const int   start = (65536 - 4 * Wl * Wl) / 3;   // 0,16384,20480,21504

    const float rx = __shfl_sync(~0u, rv, 2 * g);
    const float ry = __shfl_sync(~0u, rv, 2 * g + 1);

    const __half* valb = valh + ((size_t)b * QLEN + start) * CDIM + head * DHEAD + cp * 4;

    float4 acc = {0.f, 0.f, 0.f, 0.f};

#pragma unroll
    for (int it = 0; it < POINTS; it++) {
        const int lp = g * POINTS + it;
        const float ox = __shfl_sync(~0u, ov, 2 * lp);
        const float oy = __shfl_sync(~0u, ov, 2 * lp + 1);
        const float a  = __shfl_sync(~0u, a_reg, lp);

        // x = (rx + ox/Wf)*Wf - 0.5 == rx*Wf + ox - 0.5 (fp reassociation; error
        // feeds continuous bilinear weights -> negligible)
        const float x = fmaf(rx, Wf, ox) - 0.5f;
        const float y = fmaf(ry, Wf, oy) - 0.5f;
        const float x0f = floorf(x), y0f = floorf(y);
        const int   x0 = (int)x0f,  y0 = (int)y0f;
        const float fx = x - x0f,   fy = y - y0f;

#pragma unroll
        for (int dy = 0; dy < 2; dy++) {
            const int  yi = y0 + dy;
            const bool vy = (yi >= 0) && (yi < Wl);
            const int  yc = min(max(yi, 0), Wl - 1);
            const float wy = (dy ? fy : 1.f - fy) * a;
#pragma unroll
            for (int dx = 0; dx < 2; dx++) {
                const int  xi = x0 + dx;
                const bool vx = (xi >= 0) && (xi < Wl);
                const int  xc = min(max(xi, 0), Wl - 1);
                const float w = (vx && vy) ? (dx ? fx : 1.f - fx) * wy : 0.f;

                const uint2 raw = __ldg((const uint2*)&valb[(size_t)(yc * Wl + xc) * CDIM]);
                const float2 f01 = __half22float2(*(const __half2*)&raw.x);
                const float2 f23 = __half22float2(*(const __half2*)&raw.y);
                acc.x = fmaf(w, f01.x, acc.x);
                acc.y = fmaf(w, f01.y, acc.y);
                acc.z = fmaf(w, f23.x, acc.z);
                acc.w = fmaf(w, f23.y, acc.w);
            }
        }
    }

    // reduce across the 4 level-groups (xor over bits 3,4 of lane)
#pragma unroll
    for (int d = 8; d <= 16; d <<= 1) {
        acc.x += __shfl_xor_sync(~0u, acc.x, d);
        acc.y += __shfl_xor_sync(~0u, acc.y, d);
        acc.z += __shfl_xor_sync(~0u, acc.z, d);
        acc.w += __shfl_xor_sync(~0u, acc.w, d);
    }

    if (lane < 8) {
        const size_t o = (size_t)m * CDIM + head * DHEAD + cp * 4;
        __nv_bfloat16 h0 = __float2bfloat16(acc.x), h1 = __float2bfloat16(acc.y);
        __nv_bfloat16 h2 = __float2bfloat16(acc.z), h3 = __float2bfloat16(acc.w);
        __nv_bfloat162 hi01(h0, h1), hi23(h2, h3);
        __nv_bfloat162 lo01(__float2bfloat16(acc.x - __bfloat162float(h0)),
                            __float2bfloat16(acc.y - __bfloat162float(h1)));
        __nv_bfloat162 lo23(__float2bfloat16(acc.z - __bfloat162float(h2)),
                            __float2bfloat16(acc.w - __bfloat162float(h3)));
        uint2 hp, lp2;
        hp.x = *(uint32_t*)&hi01; hp.y = *(uint32_t*)&hi23;
        lp2.x = *(uint32_t*)&lo01; lp2.y = *(uint32_t*)&lo23;
        *(uint2*)&shi[o] = hp;
        *(uint2*)&slo[o] = lp2;
    }
}

// ---------------------------------------------------------------------------
// Launch
// ---------------------------------------------------------------------------
extern "C" void kernel_launch(void* const* d_in, const int* in_sizes, int n_in,
                              void* d_out, int out_size)
{
    const float* query  = (const float*)d_in[0];
    const float* value  = (const float*)d_in[1];
    const float* refpts = (const float*)d_in[2];
    const float* W_off  = (const float*)d_in[4];
    const float* b_off  = (const float*)d_in[5];
    const float* W_attn = (const float*)d_in[6];
    const float* b_attn = (const float*)d_in[7];
    const float* W_v    = (const float*)d_in[8];
    const float* b_v    = (const float*)d_in[9];
    const float* W_out  = (const float*)d_in[10];
    const float* b_out  = (const float*)d_in[11];
    float* out = (float*)d_out;

    float *off, *attn; __half* valh;
    cudaGetSymbolAddress((void**)&valh, g_val_h);
    cudaGetSymbolAddress((void**)&off,  g_off);
    cudaGetSymbolAddress((void**)&attn, g_attn);
    __nv_bfloat16 *vhi, *vlo, *qhi, *qlo, *shi, *slo;
    cudaGetSymbolAddress((void**)&vhi, g_val_hi); cudaGetSymbolAddress((void**)&vlo, g_val_lo);
    cudaGetSymbolAddress((void**)&qhi, g_q_hi);   cudaGetSymbolAddress((void**)&qlo, g_q_lo);
    cudaGetSymbolAddress((void**)&shi, g_s_hi);   cudaGetSymbolAddress((void**)&slo, g_s_lo);
    __nv_bfloat16 *wvh, *wvl, *woh, *wol, *wah, *wal, *wuh, *wul;
    cudaGetSymbolAddress((void**)&wvh, g_wv_hi);   cudaGetSymbolAddress((void**)&wvl, g_wv_lo);
    cudaGetSymbolAddress((void**)&woh, g_woff_hi); cudaGetSymbolAddress((void**)&wol, g_woff_lo);
    cudaGetSymbolAddress((void**)&wah, g_wat_hi);  cudaGetSymbolAddress((void**)&wal, g_wat_lo);
    cudaGetSymbolAddress((void**)&wuh, g_wout_hi); cudaGetSymbolAddress((void**)&wul, g_wout_lo);

    cudaFuncSetAttribute(mma_gemm, cudaFuncAttributeMaxDynamicSharedMemorySize, GEMM_SMEM_BYTES);

    // L0: fused weight transpose+split
    transpose_split_all<<<dim3(256, 4), 256>>>(W_v, W_off, W_attn, W_out,
                                               wvh, wvl, woh, wol, wah, wal, wuh, wul);
    // L1: fused value+query split
    {
        int n4 = MROWS * CDIM / 4;
        split_all_kernel<<<dim3((n4 + 255) / 256, 2), 256>>>(value, query,
                                                             vhi, vlo, qhi, qlo, n4);
    }

    dim3 blk(256);
    dim3 gridN256(MROWS / 128, 2);
    dim3 gridN128(MROWS / 128, 1);

    // L2: value projection -> fp16 table
    mma_gemm<<<gridN256, blk, GEMM_SMEM_BYTES>>>(vhi, vlo, wvh, wvl, b_v, nullptr, valh, 256);
    // L3: offsets
    mma_gemm<<<gridN256, blk, GEMM_SMEM_BYTES>>>(qhi, qlo, woh, wol, b_off, off, nullptr, 256);
    // L4: attn logits
    mma_gemm<<<gridN128, blk, GEMM_SMEM_BYTES>>>(qhi, qlo, wah, wal, b_attn, attn, nullptr, 128);
    // L5: sampler
    sample_kernel<<<MROWS, HEADS * 32>>>(valh, off, attn, refpts, shi, slo);
    // L6: output projection
    mma_gemm<<<gridN256, blk, GEMM_SMEM_BYTES>>>(shi, slo, wuh, wul, b_out, out, nullptr, 256);
}

// round 7
// speedup vs baseline: 2.7476x; 1.1959x over previous
#include <cuda_runtime.h>
#include <cuda_fp16.h>
#include <cstdint>
#include <math.h>

// ---------------------------------------------------------------------------
// Problem constants
// ---------------------------------------------------------------------------
#define BS      2
#define QLEN    21760            // 128^2 + 64^2 + 32^2 + 16^2
#define MROWS   (BS * QLEN)      // 43520
#define CDIM    256
#define HEADS   8
#define DHEAD   32
#define LEVELS  4
#define POINTS  4
#define NOA     384              // concat: 256 offsets + 128 attn logits

// ---------------------------------------------------------------------------
// Scratch (static device globals)
// ---------------------------------------------------------------------------
__device__ __half g_val_h[MROWS * CDIM];      // value @ W_v + b_v (fp16 table)
__device__ float  g_oa  [MROWS * NOA];        // [m][0:256]=offsets, [256:384]=logits
__device__ __half g_v16 [MROWS * CDIM];       // value fp16 (GEMM A)
__device__ __half g_q16 [MROWS * CDIM];       // query fp16 (GEMM A)
__device__ __half g_s16 [MROWS * CDIM];       // sampled fp16 (GEMM A)

// Transposed weights [N, K=256] fp16 hi/lo
__device__ __half g_wv_hi [CDIM * CDIM], g_wv_lo [CDIM * CDIM];
__device__ __half g_oa_hi [NOA  * CDIM], g_oa_lo [NOA  * CDIM];
__device__ __half g_wu_hi [CDIM * CDIM], g_wu_lo [CDIM * CDIM];
__device__ float  g_bias_oa[NOA];

// ---------------------------------------------------------------------------
// Helpers
// ---------------------------------------------------------------------------
__device__ __forceinline__ uint32_t smem_u32(const void* p) {
    uint32_t a;
    asm("{ .reg .u64 t; cvta.to.shared.u64 t, %1; cvt.u32.u64 %0, t; }" : "=r"(a) : "l"(p));
    return a;
}
#define SMEM_SWZ64(off) ((off) ^ (((off) >> 3) & 0x30))

__device__ __forceinline__ void ldsm4(uint32_t& r0, uint32_t& r1, uint32_t& r2, uint32_t& r3,
                                      uint32_t addr) {
    asm volatile("ldmatrix.sync.aligned.m8n8.x4.shared.b16 {%0,%1,%2,%3}, [%4];"
                 : "=r"(r0), "=r"(r1), "=r"(r2), "=r"(r3) : "r"(addr));
}
__device__ __forceinline__ void mma_f16(float* d, const uint32_t* a, const uint32_t* b) {
    asm volatile(
        "mma.sync.aligned.m16n8k16.row.col.f32.f16.f16.f32 "
        "{%0,%1,%2,%3}, {%4,%5,%6,%7}, {%8,%9}, {%0,%1,%2,%3};"
        : "+f"(d[0]), "+f"(d[1]), "+f"(d[2]), "+f"(d[3])
        : "r"(a[0]), "r"(a[1]), "r"(a[2]), "r"(a[3]), "r"(b[0]), "r"(b[1]));
}
#define CP_ASYNC16(dst_u32, src_ptr) \
    asm volatile("cp.async.cg.shared.global [%0], [%1], 16;" :: "r"(dst_u32), "l"(src_ptr))
#define CP_COMMIT()  asm volatile("cp.async.commit_group;" ::: "memory")
#define CP_WAIT1()   asm volatile("cp.async.wait_group 1;" ::: "memory")
#define CP_WAIT0()   asm volatile("cp.async.wait_group 0;" ::: "memory")

// ---------------------------------------------------------------------------
// Prep: fp32 -> fp16 conversion for value & query (GEMM A operands)
// ---------------------------------------------------------------------------
__global__ void to_half_kernel(const float* __restrict__ value,
                               const float* __restrict__ query,
                               __half* __restrict__ vh, __half* __restrict__ qh, int n4)
{
    int i = blockIdx.x * blockDim.x + threadIdx.x;
    if (i >= n4) return;
    const float* x = blockIdx.y ? query : value;
    __half* o = blockIdx.y ? qh : vh;
    float4 v = ((const float4*)x)[i];
    __half2 h01 = __floats2half2_rn(v.x, v.y);
    __half2 h23 = __floats2half2_rn(v.z, v.w);
    uint2 pk; pk.x = *(uint32_t*)&h01; pk.y = *(uint32_t*)&h23;
    ((uint2*)o)[i] = pk;
}

// Weights: transpose + fp16 hi/lo split. which=0: W_v, 1: [W_off|W_attn], 2: W_out
__global__ void prep_weights(const float* __restrict__ Wv,
                             const float* __restrict__ Woff,
                             const float* __restrict__ Wattn,
                             const float* __restrict__ Wout,
                             const float* __restrict__ b_off,
                             const float* __restrict__ b_attn,
                             __half* __restrict__ vh, __half* __restrict__ vl,
                             __half* __restrict__ oh, __half* __restrict__ ol,
                             __half* __restrict__ uh, __half* __restrict__ ul,
                             float* __restrict__ bias_oa)
{
    const int which = blockIdx.y;
    const int n = blockIdx.x;
    const int k = threadIdx.x;
    float v; __half *th, *tl;
    if (which == 0) {
        if (n >= CDIM) return;
        v = Wv[k * CDIM + n]; th = vh; tl = vl;
    } else if (which == 1) {
        v = (n < 256) ? Woff[k * 256 + n] : Wattn[k * 128 + (n - 256)];
        th = oh; tl = ol;
        if (k == 0) bias_oa[n] = (n < 256) ? b_off[n] : b_attn[n - 256];
    } else {
        if (n >= CDIM) return;
        v = Wout[k * CDIM + n]; th = uh; tl = ul;
    }
    __half h = __float2half_rn(v);
    th[n * 256 + k] = h;
    tl[n * 256 + k] = __float2half_rn(v - __half2float(h));
}

// ---------------------------------------------------------------------------
// HMMA GEMM (fp16, 2-pass): C[M,N] = A[M,256] @ (Bh+Bl)[N,256]^T + bias
// CTA 128x128, 8 warps (4x2). K chunks of 32, 2-stage cp.async, SW64 smem.
// Out: fp32 C or fp16 Ch.
// ---------------------------------------------------------------------------
#define STAGE_BYTES 24576                      // A 8KB + Bh 8KB + Bl 8KB
#define GEMM_SMEM_BYTES (2 * STAGE_BYTES)

__global__ __launch_bounds__(256, 2)
void mma_gemm(const __half* __restrict__ A,
              const __half* __restrict__ Bh, const __half* __restrict__ Bl,
              const float* __restrict__ bias, float* __restrict__ C,
              __half* __restrict__ Ch, int Ncols)
{
    extern __shared__ char smem[];
    const uint32_t sb = smem_u32(smem);

    const int tid  = threadIdx.x;
    const int lane = tid & 31;
    const int wid  = tid >> 5;
    const int wm   = wid & 3;
    const int wn   = wid >> 2;
    const int mtile = blockIdx.x * 128;
    const int ntile = blockIdx.y * 128;

    float acc[2][8][4];
#pragma unroll
    for (int i = 0; i < 2; i++)
#pragma unroll
        for (int j = 0; j < 8; j++)
#pragma unroll
            for (int k = 0; k < 4; k++) acc[i][j][k] = 0.f;

    const int a_row = wm * 32 + (lane & 7) + ((lane >> 3) & 1) * 8;
    const int a_sg  = (lane >> 4);
    const int b_row = wn * 64 + (lane & 7) + (lane >> 4) * 8;
    const int b_sg  = ((lane >> 3) & 1);

#define LOAD_STAGE(cc, buf) do {                                                   \
    const uint32_t st = sb + (buf) * STAGE_BYTES;                                  \
    const int kc = (cc) * 32;                                                      \
    _Pragma("unroll")                                                              \
    for (int it = 0; it < 2; it++) {                                               \
        int idx = it * 256 + tid;                                                  \
        int row = idx >> 2, seg = idx & 3;                                         \
        uint32_t so = SMEM_SWZ64((uint32_t)(row * 64 + seg * 16));                 \
        size_t ga = (size_t)(mtile + row) * 256 + kc + seg * 8;                    \
        size_t gb = (size_t)(ntile + row) * 256 + kc + seg * 8;                    \
        CP_ASYNC16(st + so,         A  + ga);                                      \
        CP_ASYNC16(st + 8192 + so,  Bh + gb);                                      \
        CP_ASYNC16(st + 16384 + so, Bl + gb);                                      \
    }                                                                              \
} while (0)

    LOAD_STAGE(0, 0);
    CP_COMMIT();

#pragma unroll 1
    for (int c = 0; c < 8; c++) {
        if (c < 7) {
            LOAD_STAGE(c + 1, (c + 1) & 1);
            CP_COMMIT();
            CP_WAIT1();
        } else {
            CP_WAIT0();
        }
        __syncthreads();

        const uint32_t st  = sb + (c & 1) * STAGE_BYTES;
        const uint32_t sA = st, sBh = st + 8192, sBl = st + 16384;

#pragma unroll
        for (int ks = 0; ks < 2; ks++) {
            uint32_t a[2][4];
#pragma unroll
            for (int mt = 0; mt < 2; mt++) {
                uint32_t off = SMEM_SWZ64((uint32_t)((a_row + mt * 16) * 64 +
                                                     (a_sg + ks * 2) * 16));
                ldsm4(a[mt][0], a[mt][1], a[mt][2], a[mt][3], sA + off);
            }
#pragma unroll
            for (int nt2 = 0; nt2 < 4; nt2++) {
                uint32_t off = SMEM_SWZ64((uint32_t)((b_row + nt2 * 16) * 64 +
                                                     (b_sg + ks * 2) * 16));
                uint32_t bh[4], bl[4];
                ldsm4(bh[0], bh[1], bh[2], bh[3], sBh + off);
                ldsm4(bl[0], bl[1], bl[2], bl[3], sBl + off);
#pragma unroll
                for (int mt = 0; mt < 2; mt++)
#pragma unroll
                    for (int half = 0; half < 2; half++) {
                        float* a4 = acc[mt][nt2 * 2 + half];
                        mma_f16(a4, a[mt], &bh[half * 2]);
                        mma_f16(a4, a[mt], &bl[half * 2]);
                    }
            }
        }
        __syncthreads();
    }
#undef LOAD_STAGE

    if (Ch) {
#pragma unroll
        for (int mt = 0; mt < 2; mt++) {
            const int r0 = mtile + wm * 32 + mt * 16 + (lane >> 2);
#pragma unroll
            for (int nt = 0; nt < 8; nt++) {
                const int cc = ntile + wn * 64 + nt * 8 + (lane & 3) * 2;
                const float bx = __ldg(bias + cc), by = __ldg(bias + cc + 1);
                __half2 h0 = __floats2half2_rn(acc[mt][nt][0] + bx, acc[mt][nt][1] + by);
                __half2 h1 = __floats2half2_rn(acc[mt][nt][2] + bx, acc[mt][nt][3] + by);
                *(__half2*)&Ch[(size_t)r0       * Ncols + cc] = h0;
                *(__half2*)&Ch[(size_t)(r0 + 8) * Ncols + cc] = h1;
            }
        }
    } else {
#pragma unroll
        for (int mt = 0; mt < 2; mt++) {
            const int r0 = mtile + wm * 32 + mt * 16 + (lane >> 2);
#pragma unroll
            for (int nt = 0; nt < 8; nt++) {
                const int cc = ntile + wn * 64 + nt * 8 + (lane & 3) * 2;
                const float bx = __ldg(bias + cc), by = __ldg(bias + cc + 1);
                float2 o0 = {acc[mt][nt][0] + bx, acc[mt][nt][1] + by};
                float2 o1 = {acc[mt][nt][2] + bx, acc[mt][nt][3] + by};
                *(float2*)&C[(size_t)r0       * Ncols + cc] = o0;
                *(float2*)&C[(size_t)(r0 + 8) * Ncols + cc] = o1;
            }
        }
    }
}

// ---------------------------------------------------------------------------
// Deformable sampling (vectorized): warp = head, lane -> (level, chan-quad).
// Offsets+logits come from the fused [m][384] buffer. Output: fp16.
// ---------------------------------------------------------------------------
__global__ __launch_bounds__(HEADS * 32)
void sample_kernel(const __half* __restrict__ valh,
                   const float* __restrict__ oa,
                   const float* __restrict__ ref,
                   __half* __restrict__ sout)
{
    const int q    = blockIdx.x;
    const int b    = blockIdx.y;
    const int m    = b * QLEN + q;
    const int head = threadIdx.x >> 5;
    const int lane = threadIdx.x & 31;
    const int g    = lane >> 3;        // level group
    const int cp   = lane & 7;         // channel quad

    // softmax over this head's 16 logits
    const float* row = oa + (size_t)m * NOA;
    float lg = __ldg(&row[256 + head * 16 + (lane & 15)]);
    float mx = lg;
#pragma unroll
    for (int d = 1; d < 16; d <<= 1) mx = fmaxf(mx, __shfl_xor_sync(~0u, mx, d));
    float e = __expf(lg - mx);
    float s = e;
#pragma unroll
    for (int d = 1; d < 16; d <<= 1) s += __shfl_xor_sync(~0u, s, d);
    const float a_reg = e / s;

    const float ov = __ldg(&row[head * 32 + lane]);
    const float rv = __ldg(&ref[(size_t)m * (LEVELS * 2) + (lane & 7)]);

    const int   Wl = 128 >> g;
    const float Wf = (float)Wl;
    const int   start = (65536 - 4 * Wl * Wl) / 3;   // 0,16384,20480,21504

    const float rx = __shfl_sync(~0u, rv, 2 * g);
    const float ry = __shfl_sync(~0u, rv, 2 * g + 1);

    const __half* valb = valh + ((size_t)b * QLEN + start) * CDIM + head * DHEAD + cp * 4;

    float4 acc = {0.f, 0.f, 0.f, 0.f};

#pragma unroll
    for (int it = 0; it < POINTS; it++) {
        const int lp = g * POINTS + it;
        const float ox = __shfl_sync(~0u, ov, 2 * lp);
        const float oy = __shfl_sync(~0u, ov, 2 * lp + 1);
        const float a  = __shfl_sync(~0u, a_reg, lp);

        const float x = fmaf(rx, Wf, ox) - 0.5f;
        const float y = fmaf(ry, Wf, oy) - 0.5f;
        const float x0f = floorf(x), y0f = floorf(y);
        const int   x0 = (int)x0f,  y0 = (int)y0f;
        const float fx = x - x0f,   fy = y - y0f;

#pragma unroll
        for (int dy = 0; dy < 2; dy++) {
            const int  yi = y0 + dy;
            const bool vy = (yi >= 0) && (yi < Wl);
            const int  yc = min(max(yi, 0), Wl - 1);
            const float wy = (dy ? fy : 1.f - fy) * a;
#pragma unroll
            for (int dx = 0; dx < 2; dx++) {
                const int  xi = x0 + dx;
                const bool vx = (xi >= 0) && (xi < Wl);
                const int  xc = min(max(xi, 0), Wl - 1);
                const float w = (vx && vy) ? (dx ? fx : 1.f - fx) * wy : 0.f;

                const uint2 raw = __ldg((const uint2*)&valb[(size_t)(yc * Wl + xc) * CDIM]);
                const float2 f01 = __half22float2(*(const __half2*)&raw.x);
                const float2 f23 = __half22float2(*(const __half2*)&raw.y);
                acc.x = fmaf(w, f01.x, acc.x);
                acc.y = fmaf(w, f01.y, acc.y);
                acc.z = fmaf(w, f23.x, acc.z);
                acc.w = fmaf(w, f23.y, acc.w);
            }
        }
    }

    // reduce across the 4 level-groups
#pragma unroll
    for (int d = 8; d <= 16; d <<= 1) {
        acc.x += __shfl_xor_sync(~0u, acc.x, d);
        acc.y += __shfl_xor_sync(~0u, acc.y, d);
        acc.z += __shfl_xor_sync(~0u, acc.z, d);
        acc.w += __shfl_xor_sync(~0u, acc.w, d);
    }

    if (lane < 8) {
        const size_t o = (size_t)m * CDIM + head * DHEAD + cp * 4;
        __half2 h01 = __floats2half2_rn(acc.x, acc.y);
        __half2 h23 = __floats2half2_rn(acc.z, acc.w);
        uint2 pk; pk.x = *(uint32_t*)&h01; pk.y = *(uint32_t*)&h23;
        *(uint2*)&sout[o] = pk;
    }
}

// ---------------------------------------------------------------------------
// Launch
// ---------------------------------------------------------------------------
extern "C" void kernel_launch(void* const* d_in, const int* in_sizes, int n_in,
                              void* d_out, int out_size)
{
    const float* query  = (const float*)d_in[0];
    const float* value  = (const float*)d_in[1];
    const float* refpts = (const float*)d_in[2];
    const float* W_off  = (const float*)d_in[4];
    const float* b_off  = (const float*)d_in[5];
    const float* W_attn = (const float*)d_in[6];
    const float* b_attn = (const float*)d_in[7];
    const float* W_v    = (const float*)d_in[8];
    const float* b_v    = (const float*)d_in[9];
    const float* W_out  = (const float*)d_in[10];
    const float* b_out  = (const float*)d_in[11];
    float* out = (float*)d_out;

    __half *valh, *v16, *q16, *s16;
    float *oa, *bias_oa;
    cudaGetSymbolAddress((void**)&valh, g_val_h);
    cudaGetSymbolAddress((void**)&oa,   g_oa);
    cudaGetSymbolAddress((void**)&v16,  g_v16);
    cudaGetSymbolAddress((void**)&q16,  g_q16);
    cudaGetSymbolAddress((void**)&s16,  g_s16);
    cudaGetSymbolAddress((void**)&bias_oa, g_bias_oa);
    __half *wvh, *wvl, *oah, *oal, *wuh, *wul;
    cudaGetSymbolAddress((void**)&wvh, g_wv_hi); cudaGetSymbolAddress((void**)&wvl, g_wv_lo);
    cudaGetSymbolAddress((void**)&oah, g_oa_hi); cudaGetSymbolAddress((void**)&oal, g_oa_lo);
    cudaGetSymbolAddress((void**)&wuh, g_wu_hi); cudaGetSymbolAddress((void**)&wul, g_wu_lo);

    cudaFuncSetAttribute(mma_gemm, cudaFuncAttributeMaxDynamicSharedMemorySize, GEMM_SMEM_BYTES);

    // L0: weight transpose + hi/lo split + bias concat
    prep_weights<<<dim3(NOA, 3), 256>>>(W_v, W_off, W_attn, W_out, b_off, b_attn,
                                        wvh, wvl, oah, oal, wuh, wul, bias_oa);
    // L1: value/query fp32 -> fp16
    {
        int n4 = MROWS * CDIM / 4;
        to_half_kernel<<<dim3((n4 + 255) / 256, 2), 256>>>(value, query, v16, q16, n4);
    }

    dim3 blk(256);
    dim3 gridV(MROWS / 128, 2);    // N=256
    dim3 gridOA(MROWS / 128, 3);   // N=384
    dim3 gridO(MROWS / 128, 2);    // N=256

    // L2: value projection -> fp16 table
    mma_gemm<<<gridV, blk, GEMM_SMEM_BYTES>>>(v16, wvh, wvl, b_v, nullptr, valh, 256);
    // L3: offsets + attn logits (fused, N=384)
    mma_gemm<<<gridOA, blk, GEMM_SMEM_BYTES>>>(q16, oah, oal, bias_oa, oa, nullptr, NOA);
    // L4: sampler -> fp16
    sample_kernel<<<dim3(QLEN, BS), HEADS * 32>>>(valh, oa, refpts, s16);
    // L5: output projection
    mma_gemm<<<gridO, blk, GEMM_SMEM_BYTES>>>(s16, wuh, wul, b_out, out, nullptr, 256);
}

// round 8
// speedup vs baseline: 2.9235x; 1.0640x over previous
#include <cuda_runtime.h>
#include <cuda_fp16.h>
#include <cstdint>
#include <math.h>

// ---------------------------------------------------------------------------
// Problem constants
// ---------------------------------------------------------------------------
#define BS      2
#define QLEN    21760            // 128^2 + 64^2 + 32^2 + 16^2
#define MROWS   (BS * QLEN)      // 43520
#define CDIM    256
#define HEADS   8
#define DHEAD   32
#define LEVELS  4
#define POINTS  4
#define NOA     384              // concat: 256 offsets + 128 attn logits

// ---------------------------------------------------------------------------
// Scratch (static device globals)
// ---------------------------------------------------------------------------
__device__ __half g_val_h[MROWS * CDIM];      // value @ W_v + b_v (fp16 table)
__device__ float  g_oa  [MROWS * NOA];        // [m][0:256]=offsets, [256:384]=logits
__device__ __half g_v16 [MROWS * CDIM];       // value fp16 (GEMM A)
__device__ __half g_q16 [MROWS * CDIM];       // query fp16 (GEMM A)
__device__ __half g_s16 [MROWS * CDIM];       // sampled fp16 (GEMM A)

// Transposed weights [N, K=256] fp16 hi/lo
__device__ __half g_wv_hi [CDIM * CDIM], g_wv_lo [CDIM * CDIM];
__device__ __half g_oa_hi [NOA  * CDIM], g_oa_lo [NOA  * CDIM];
__device__ __half g_wu_hi [CDIM * CDIM], g_wu_lo [CDIM * CDIM];
__device__ float  g_bias_oa[NOA];

// ---------------------------------------------------------------------------
// Helpers
// ---------------------------------------------------------------------------
__device__ __forceinline__ uint32_t smem_u32(const void* p) {
    uint32_t a;
    asm("{ .reg .u64 t; cvta.to.shared.u64 t, %1; cvt.u32.u64 %0, t; }" : "=r"(a) : "l"(p));
    return a;
}
#define SMEM_SWZ64(off) ((off) ^ (((off) >> 3) & 0x30))

__device__ __forceinline__ void ldsm4(uint32_t& r0, uint32_t& r1, uint32_t& r2, uint32_t& r3,
                                      uint32_t addr) {
    asm volatile("ldmatrix.sync.aligned.m8n8.x4.shared.b16 {%0,%1,%2,%3}, [%4];"
                 : "=r"(r0), "=r"(r1), "=r"(r2), "=r"(r3) : "r"(addr));
}
__device__ __forceinline__ void mma_f16(float* d, const uint32_t* a, const uint32_t* b) {
    asm volatile(
        "mma.sync.aligned.m16n8k16.row.col.f32.f16.f16.f32 "
        "{%0,%1,%2,%3}, {%4,%5,%6,%7}, {%8,%9}, {%0,%1,%2,%3};"
        : "+f"(d[0]), "+f"(d[1]), "+f"(d[2]), "+f"(d[3])
        : "r"(a[0]), "r"(a[1]), "r"(a[2]), "r"(a[3]), "r"(b[0]), "r"(b[1]));
}
#define CP_ASYNC16(dst_u32, src_ptr) \
    asm volatile("cp.async.cg.shared.global [%0], [%1], 16;" :: "r"(dst_u32), "l"(src_ptr))
#define CP_COMMIT()  asm volatile("cp.async.commit_group;" ::: "memory")
#define CP_WAIT1()   asm volatile("cp.async.wait_group 1;" ::: "memory")
#define CP_WAIT0()   asm volatile("cp.async.wait_group 0;" ::: "memory")

// ---------------------------------------------------------------------------
// Prep: fp32 -> fp16 conversion for value & query (GEMM A operands)
// ---------------------------------------------------------------------------
__global__ void to_half_kernel(const float* __restrict__ value,
                               const float* __restrict__ query,
                               __half* __restrict__ vh, __half* __restrict__ qh, int n4)
{
    int i = blockIdx.x * blockDim.x + threadIdx.x;
    if (i >= n4) return;
    const float* x = blockIdx.y ? query : value;
    __half* o = blockIdx.y ? qh : vh;
    float4 v = ((const float4*)x)[i];
    __half2 h01 = __floats2half2_rn(v.x, v.y);
    __half2 h23 = __floats2half2_rn(v.z, v.w);
    uint2 pk; pk.x = *(uint32_t*)&h01; pk.y = *(uint32_t*)&h23;
    ((uint2*)o)[i] = pk;
}

// Weights: transpose + fp16 hi/lo split. which=0: W_v, 1: [W_off|W_attn], 2: W_out
__global__ void prep_weights(const float* __restrict__ Wv,
                             const float* __restrict__ Woff,
                             const float* __restrict__ Wattn,
                             const float* __restrict__ Wout,
                             const float* __restrict__ b_off,
                             const float* __restrict__ b_attn,
                             __half* __restrict__ vh, __half* __restrict__ vl,
                             __half* __restrict__ oh, __half* __restrict__ ol,
                             __half* __restrict__ uh, __half* __restrict__ ul,
                             float* __restrict__ bias_oa)
{
    const int which = blockIdx.y;
    const int n = blockIdx.x;
    const int k = threadIdx.x;
    float v; __half *th, *tl;
    if (which == 0) {
        if (n >= CDIM) return;
        v = Wv[k * CDIM + n]; th = vh; tl = vl;
    } else if (which == 1) {
        v = (n < 256) ? Woff[k * 256 + n] : Wattn[k * 128 + (n - 256)];
        th = oh; tl = ol;
        if (k == 0) bias_oa[n] = (n < 256) ? b_off[n] : b_attn[n - 256];
    } else {
        if (n >= CDIM) return;
        v = Wout[k * CDIM + n]; th = uh; tl = ul;
    }
    __half h = __float2half_rn(v);
    th[n * 256 + k] = h;
    tl[n * 256 + k] = __float2half_rn(v - __half2float(h));
}

// ---------------------------------------------------------------------------
// HMMA GEMM (fp16, 2-pass): unchanged from R7.
// ---------------------------------------------------------------------------
#define STAGE_BYTES 24576
#define GEMM_SMEM_BYTES (2 * STAGE_BYTES)

__global__ __launch_bounds__(256, 2)
void mma_gemm(const __half* __restrict__ A,
              const __half* __restrict__ Bh, const __half* __restrict__ Bl,
              const float* __restrict__ bias, float* __restrict__ C,
              __half* __restrict__ Ch, int Ncols)
{
    extern __shared__ char smem[];
    const uint32_t sb = smem_u32(smem);

    const int tid  = threadIdx.x;
    const int lane = tid & 31;
    const int wid  = tid >> 5;
    const int wm   = wid & 3;
    const int wn   = wid >> 2;
    const int mtile = blockIdx.x * 128;
    const int ntile = blockIdx.y * 128;

    float acc[2][8][4];
#pragma unroll
    for (int i = 0; i < 2; i++)
#pragma unroll
        for (int j = 0; j < 8; j++)
#pragma unroll
            for (int k = 0; k < 4; k++) acc[i][j][k] = 0.f;

    const int a_row = wm * 32 + (lane & 7) + ((lane >> 3) & 1) * 8;
    const int a_sg  = (lane >> 4);
    const int b_row = wn * 64 + (lane & 7) + (lane >> 4) * 8;
    const int b_sg  = ((lane >> 3) & 1);

#define LOAD_STAGE(cc, buf) do {                                                   \
    const uint32_t st = sb + (buf) * STAGE_BYTES;                                  \
    const int kc = (cc) * 32;                                                      \
    _Pragma("unroll")                                                              \
    for (int it = 0; it < 2; it++) {                                               \
        int idx = it * 256 + tid;                                                  \
        int row = idx >> 2, seg = idx & 3;                                         \
        uint32_t so = SMEM_SWZ64((uint32_t)(row * 64 + seg * 16));                 \
        size_t ga = (size_t)(mtile + row) * 256 + kc + seg * 8;                    \
        size_t gb = (size_t)(ntile + row) * 256 + kc + seg * 8;                    \
        CP_ASYNC16(st + so,         A  + ga);                                      \
        CP_ASYNC16(st + 8192 + so,  Bh + gb);                                      \
        CP_ASYNC16(st + 16384 + so, Bl + gb);                                      \
    }                                                                              \
} while (0)

    LOAD_STAGE(0, 0);
    CP_COMMIT();

#pragma unroll 1
    for (int c = 0; c < 8; c++) {
        if (c < 7) {
            LOAD_STAGE(c + 1, (c + 1) & 1);
            CP_COMMIT();
            CP_WAIT1();
        } else {
            CP_WAIT0();
        }
        __syncthreads();

        const uint32_t st  = sb + (c & 1) * STAGE_BYTES;
        const uint32_t sA = st, sBh = st + 8192, sBl = st + 16384;

#pragma unroll
        for (int ks = 0; ks < 2; ks++) {
            uint32_t a[2][4];
#pragma unroll
            for (int mt = 0; mt < 2; mt++) {
                uint32_t off = SMEM_SWZ64((uint32_t)((a_row + mt * 16) * 64 +
                                                     (a_sg + ks * 2) * 16));
                ldsm4(a[mt][0], a[mt][1], a[mt][2], a[mt][3], sA + off);
            }
#pragma unroll
            for (int nt2 = 0; nt2 < 4; nt2++) {
                uint32_t off = SMEM_SWZ64((uint32_t)((b_row + nt2 * 16) * 64 +
                                                     (b_sg + ks * 2) * 16));
                uint32_t bh[4], bl[4];
                ldsm4(bh[0], bh[1], bh[2], bh[3], sBh + off);
                ldsm4(bl[0], bl[1], bl[2], bl[3], sBl + off);
#pragma unroll
                for (int mt = 0; mt < 2; mt++)
#pragma unroll
                    for (int half = 0; half < 2; half++) {
                        float* a4 = acc[mt][nt2 * 2 + half];
                        mma_f16(a4, a[mt], &bh[half * 2]);
                        mma_f16(a4, a[mt], &bl[half * 2]);
                    }
            }
        }
        __syncthreads();
    }
#undef LOAD_STAGE

    if (Ch) {
#pragma unroll
        for (int mt = 0; mt < 2; mt++) {
            const int r0 = mtile + wm * 32 + mt * 16 + (lane >> 2);
#pragma unroll
            for (int nt = 0; nt < 8; nt++) {
                const int cc = ntile + wn * 64 + nt * 8 + (lane & 3) * 2;
                const float bx = __ldg(bias + cc), by = __ldg(bias + cc + 1);
                __half2 h0 = __floats2half2_rn(acc[mt][nt][0] + bx, acc[mt][nt][1] + by);
                __half2 h1 = __floats2half2_rn(acc[mt][nt][2] + bx, acc[mt][nt][3] + by);
                *(__half2*)&Ch[(size_t)r0       * Ncols + cc] = h0;
                *(__half2*)&Ch[(size_t)(r0 + 8) * Ncols + cc] = h1;
            }
        }
    } else {
#pragma unroll
        for (int mt = 0; mt < 2; mt++) {
            const int r0 = mtile + wm * 32 + mt * 16 + (lane >> 2);
#pragma unroll
            for (int nt = 0; nt < 8; nt++) {
                const int cc = ntile + wn * 64 + nt * 8 + (lane & 3) * 2;
                const float bx = __ldg(bias + cc), by = __ldg(bias + cc + 1);
                float2 o0 = {acc[mt][nt][0] + bx, acc[mt][nt][1] + by};
                float2 o1 = {acc[mt][nt][2] + bx, acc[mt][nt][3] + by};
                *(float2*)&C[(size_t)r0       * Ncols + cc] = o0;
                *(float2*)&C[(size_t)(r0 + 8) * Ncols + cc] = o1;
            }
        }
    }
}

// ---------------------------------------------------------------------------
// Deformable sampling v3: warp = head; lane -> (group g = lane>>2, octet c4).
// 8 groups process 8 corners per warp-instruction; lane gathers 8 channels
// via LDG.128. Group g: level l = g>>1, point-half h = g&1 (2 points each).
// ---------------------------------------------------------------------------
__global__ __launch_bounds__(HEADS * 32)
void sample_kernel(const __half* __restrict__ valh,
                   const float* __restrict__ oa,
                   const float* __restrict__ ref,
                   __half* __restrict__ sout)
{
    const int q    = blockIdx.x;
    const int b    = blockIdx.y;
    const int m    = b * QLEN + q;
    const int head = threadIdx.x >> 5;
    const int lane = threadIdx.x & 31;
    const int g    = lane >> 2;        // 8 groups of 4 lanes
    const int c4   = lane & 3;         // channel octet: channels c4*8 .. c4*8+7
    const int l    = g >> 1;           // level
    const int h    = g & 1;            // point-half (points 2h, 2h+1)

    // --- softmax over this head's 16 logits ---
    const float* row = oa + (size_t)m * NOA;
    float lg = __ldg(&row[256 + head * 16 + (lane & 15)]);
    float mx = lg;
#pragma unroll
    for (int d = 1; d < 16; d <<= 1) mx = fmaxf(mx, __shfl_xor_sync(~0u, mx, d));
    float e = __expf(lg - mx);
    float s = e;
#pragma unroll
    for (int d = 1; d < 16; d <<= 1) s += __shfl_xor_sync(~0u, s, d);
    const float a_all = e / s;          // lane i (mod 16) holds attn weight i

    const float ov = __ldg(&row[head * 32 + lane]);                  // offsets
    const float rv = __ldg(&ref[(size_t)m * (LEVELS * 2) + (lane & 7)]);

    const int   Wl = 128 >> l;
    const float Wf = (float)Wl;
    const int   start = (65536 - 4 * Wl * Wl) / 3;   // 0,16384,20480,21504

    const float rx = __shfl_sync(~0u, rv, 2 * l);
    const float ry = __shfl_sync(~0u, rv, 2 * l + 1);

    const __half* valb = valh + ((size_t)b * QLEN + start) * CDIM + head * DHEAD + c4 * 8;

    float acc[8];
#pragma unroll
    for (int i = 0; i < 8; i++) acc[i] = 0.f;

#pragma unroll
    for (int j = 0; j < 2; j++) {
        const int lp = l * 4 + h * 2 + j;               // this group's point
        const float ox = __shfl_sync(~0u, ov, 2 * lp);
        const float oy = __shfl_sync(~0u, ov, 2 * lp + 1);
        const float a  = __shfl_sync(~0u, a_all, lp);

        const float x = fmaf(rx, Wf, ox) - 0.5f;
        const float y = fmaf(ry, Wf, oy) - 0.5f;
        const float x0f = floorf(x), y0f = floorf(y);
        const int   x0 = (int)x0f,  y0 = (int)y0f;
        const float fx = x - x0f,   fy = y - y0f;

#pragma unroll
        for (int dy = 0; dy < 2; dy++) {
            const int  yi = y0 + dy;
            const bool vy = (yi >= 0) && (yi < Wl);
            const int  yc = min(max(yi, 0), Wl - 1);
            const float wy = (dy ? fy : 1.f - fy) * a;
#pragma unroll
            for (int dx = 0; dx < 2; dx++) {
                const int  xi = x0 + dx;
                const bool vx = (xi >= 0) && (xi < Wl);
                const int  xc = min(max(xi, 0), Wl - 1);
                const float w = (vx && vy) ? (dx ? fx : 1.f - fx) * wy : 0.f;

                const uint4 raw = __ldg((const uint4*)&valb[(size_t)(yc * Wl + xc) * CDIM]);
                const float2 f0 = __half22float2(*(const __half2*)&raw.x);
                const float2 f1 = __half22float2(*(const __half2*)&raw.y);
                const float2 f2 = __half22float2(*(const __half2*)&raw.z);
                const float2 f3 = __half22float2(*(const __half2*)&raw.w);
                acc[0] = fmaf(w, f0.x, acc[0]);
                acc[1] = fmaf(w, f0.y, acc[1]);
                acc[2] = fmaf(w, f1.x, acc[2]);
                acc[3] = fmaf(w, f1.y, acc[3]);
                acc[4] = fmaf(w, f2.x, acc[4]);
                acc[5] = fmaf(w, f2.y, acc[5]);
                acc[6] = fmaf(w, f3.x, acc[6]);
                acc[7] = fmaf(w, f3.y, acc[7]);
            }
        }
    }

    // reduce across the 8 groups (xor over bits 2,3,4 of lane)
#pragma unroll
    for (int d = 4; d <= 16; d <<= 1)
#pragma unroll
        for (int i = 0; i < 8; i++)
            acc[i] += __shfl_xor_sync(~0u, acc[i], d);

    if (lane < 4) {
        const size_t o = (size_t)m * CDIM + head * DHEAD + c4 * 8;
        __half2 h0 = __floats2half2_rn(acc[0], acc[1]);
        __half2 h1 = __floats2half2_rn(acc[2], acc[3]);
        __half2 h2 = __floats2half2_rn(acc[4], acc[5]);
        __half2 h3 = __floats2half2_rn(acc[6], acc[7]);
        uint4 pk;
        pk.x = *(uint32_t*)&h0; pk.y = *(uint32_t*)&h1;
        pk.z = *(uint32_t*)&h2; pk.w = *(uint32_t*)&h3;
        *(uint4*)&sout[o] = pk;
    }
}

// ---------------------------------------------------------------------------
// Launch
// ---------------------------------------------------------------------------
extern "C" void kernel_launch(void* const* d_in, const int* in_sizes, int n_in,
                              void* d_out, int out_size)
{
    const float* query  = (const float*)d_in[0];
    const float* value  = (const float*)d_in[1];
    const float* refpts = (const float*)d_in[2];
    const float* W_off  = (const float*)d_in[4];
    const float* b_off  = (const float*)d_in[5];
    const float* W_attn = (const float*)d_in[6];
    const float* b_attn = (const float*)d_in[7];
    const float* W_v    = (const float*)d_in[8];
    const float* b_v    = (const float*)d_in[9];
    const float* W_out  = (const float*)d_in[10];
    const float* b_out  = (const float*)d_in[11];
    float* out = (float*)d_out;

    __half *valh, *v16, *q16, *s16;
    float *oa, *bias_oa;
    cudaGetSymbolAddress((void**)&valh, g_val_h);
    cudaGetSymbolAddress((void**)&oa,   g_oa);
    cudaGetSymbolAddress((void**)&v16,  g_v16);
    cudaGetSymbolAddress((void**)&q16,  g_q16);
    cudaGetSymbolAddress((void**)&s16,  g_s16);
    cudaGetSymbolAddress((void**)&bias_oa, g_bias_oa);
    __half *wvh, *wvl, *oah, *oal, *wuh, *wul;
    cudaGetSymbolAddress((void**)&wvh, g_wv_hi); cudaGetSymbolAddress((void**)&wvl, g_wv_lo);
    cudaGetSymbolAddress((void**)&oah, g_oa_hi); cudaGetSymbolAddress((void**)&oal, g_oa_lo);
    cudaGetSymbolAddress((void**)&wuh, g_wu_hi); cudaGetSymbolAddress((void**)&wul, g_wu_lo);

    cudaFuncSetAttribute(mma_gemm, cudaFuncAttributeMaxDynamicSharedMemorySize, GEMM_SMEM_BYTES);

    // L0: weight transpose + hi/lo split + bias concat
    prep_weights<<<dim3(NOA, 3), 256>>>(W_v, W_off, W_attn, W_out, b_off, b_attn,
                                        wvh, wvl, oah, oal, wuh, wul, bias_oa);
    // L1: value/query fp32 -> fp16
    {
        int n4 = MROWS * CDIM / 4;
        to_half_kernel<<<dim3((n4 + 255) / 256, 2), 256>>>(value, query, v16, q16, n4);
    }

    dim3 blk(256);
    dim3 gridV(MROWS / 128, 2);    // N=256
    dim3 gridOA(MROWS / 128, 3);   // N=384
    dim3 gridO(MROWS / 128, 2);    // N=256

    // L2: value projection -> fp16 table
    mma_gemm<<<gridV, blk, GEMM_SMEM_BYTES>>>(v16, wvh, wvl, b_v, nullptr, valh, 256);
    // L3: offsets + attn logits (fused, N=384)
    mma_gemm<<<gridOA, blk, GEMM_SMEM_BYTES>>>(q16, oah, oal, bias_oa, oa, nullptr, NOA);
    // L4: sampler -> fp16
    sample_kernel<<<dim3(QLEN, BS), HEADS * 32>>>(valh, oa, refpts, s16);
    // L5: output projection
    mma_gemm<<<gridO, blk, GEMM_SMEM_BYTES>>>(s16, wuh, wul, b_out, out, nullptr, 256);
}